// round 3
// baseline (speedup 1.0000x reference)
#include <cuda_runtime.h>
#include <math.h>

// Problem constants
#define Bb   2
#define Ss   2048
#define Dd   768
#define Hh   12
#define DHd  64
#define Tt   64
#define FFd  3072
#define Rr   50

// ---------------- scratch (device globals; no allocations allowed) ----------
__device__ float g_q  [Bb*Ss*Dd];
__device__ float g_k  [Bb*Ss*Dd];
__device__ float g_v  [Bb*Ss*Dd];
__device__ float g_ctx[Bb*Ss*Dd];
__device__ float g_t1 [Bb*Ss*Dd];
__device__ float g_x1 [Bb*Ss*Dd];
__device__ float g_x2 [Bb*Ss*Dd];
__device__ float g_ck [Tt*Dd];
__device__ float g_cv [Tt*Dd];
__device__ float g_ff [Bb*Ss*FFd];

// ---------------- generic SGEMM: C = act(A[M,K] @ W[K,N] + bias (+res)) -----
// 128x128 block tile, BK=8, 256 threads, 8x8 microtile.
#define GBM 128
#define GBN 128
#define GBK 8

template<int ACT, int RES>
__global__ __launch_bounds__(256, 2)
void gemm_kernel(const float* __restrict__ A, const float* __restrict__ W,
                 const float* __restrict__ bias, const float* __restrict__ Rz,
                 float* __restrict__ C, int M, int N, int K)
{
    __shared__ float As[GBK][GBM];
    __shared__ float Ws[GBK][GBN];

    const int tid = threadIdx.x;
    const int bm = blockIdx.y * GBM;
    const int bn = blockIdx.x * GBN;
    const int tx = tid & 15;          // 16 col groups
    const int ty = tid >> 4;          // 16 row groups

    float acc[8][8];
    #pragma unroll
    for (int i = 0; i < 8; i++)
        #pragma unroll
        for (int j = 0; j < 8; j++) acc[i][j] = 0.f;

    const int arow = tid >> 1;             // 128 rows
    const int ak   = (tid & 1) * 4;        // 2 x float4 per row
    const int wrow = tid >> 5;             // 8 k-rows
    const int wcol = (tid & 31) * 4;       // 32 x float4 per k-row

    for (int k0 = 0; k0 < K; k0 += GBK) {
        float4 av;
        if (bm + arow < M)
            av = *(const float4*)&A[(long)(bm + arow) * K + k0 + ak];
        else
            av = make_float4(0.f, 0.f, 0.f, 0.f);
        As[ak+0][arow] = av.x; As[ak+1][arow] = av.y;
        As[ak+2][arow] = av.z; As[ak+3][arow] = av.w;

        *(float4*)&Ws[wrow][wcol] = *(const float4*)&W[(long)(k0 + wrow) * N + bn + wcol];
        __syncthreads();

        #pragma unroll
        for (int kk = 0; kk < GBK; kk++) {
            float a[8], b[8];
            #pragma unroll
            for (int i = 0; i < 8; i++) a[i] = As[kk][ty*8 + i];
            #pragma unroll
            for (int j = 0; j < 8; j++) b[j] = Ws[kk][tx*8 + j];
            #pragma unroll
            for (int i = 0; i < 8; i++)
                #pragma unroll
                for (int j = 0; j < 8; j++) acc[i][j] += a[i] * b[j];
        }
        __syncthreads();
    }

    #pragma unroll
    for (int i = 0; i < 8; i++) {
        int m = bm + ty*8 + i;
        if (m < M) {
            #pragma unroll
            for (int j = 0; j < 8; j++) {
                int n = bn + tx*8 + j;
                float val = acc[i][j] + bias[n];
                if (RES) val += Rz[(long)m * N + n];
                if (ACT == 1) val = 0.5f * val * (1.0f + erff(val * 0.70710678118654752f));
                C[(long)m * N + n] = val;
            }
        }
    }
}

// ---------------- attention (flash-style, fp32) -----------------------------
// grid: (Sq/64, H, B), 128 threads. Sk and band are runtime params so this
// serves both self-attn (Sk=2048, band add +1) and cross-attn (Sk=64).
#define AQ 64
#define AK 32

__global__ __launch_bounds__(128)
void attn_kernel(const float* __restrict__ Qp, const float* __restrict__ Kp,
                 const float* __restrict__ Vp, float* __restrict__ Op,
                 int Sq, int Sk, long kvbs, int band)
{
    __shared__ float Qs[AQ][DHd + 1];
    __shared__ float Ks[AK][DHd + 1];
    __shared__ float Vs[AK][DHd + 1];
    __shared__ float Ps[AQ][AK + 1];
    __shared__ float rm[AQ], rl[AQ], rc[AQ];

    const int b  = blockIdx.z;
    const int h  = blockIdx.y;
    const int q0 = blockIdx.x * AQ;
    const int tid = threadIdx.x;
    const int tx = tid & 7;    // 8 groups over K / DH columns
    const int ty = tid >> 3;   // 16 groups over Q rows

    const float* qb = Qp + ((long)b * Sq) * Dd + h * DHd;
    const float* kb = Kp + (long)b * kvbs + h * DHd;
    const float* vb = Vp + (long)b * kvbs + h * DHd;

    for (int i = tid; i < AQ * DHd; i += 128)
        Qs[i >> 6][i & 63] = qb[(long)(q0 + (i >> 6)) * Dd + (i & 63)];
    if (tid < AQ) { rm[tid] = -1e30f; rl[tid] = 0.f; }

    float Oacc[4][8];
    #pragma unroll
    for (int i = 0; i < 4; i++)
        #pragma unroll
        for (int j = 0; j < 8; j++) Oacc[i][j] = 0.f;

    const int ntiles = Sk / AK;
    for (int kt = 0; kt < ntiles; kt++) {
        const int k0 = kt * AK;
        __syncthreads();   // ensure previous-iter consumers done before overwrite
        for (int i = tid; i < AK * DHd; i += 128) {
            int r = i >> 6, c = i & 63;
            Ks[r][c] = kb[(long)(k0 + r) * Dd + c];
            Vs[r][c] = vb[(long)(k0 + r) * Dd + c];
        }
        __syncthreads();

        // scores: 4 q-rows x 4 k-cols per thread
        float sacc[4][4];
        #pragma unroll
        for (int i = 0; i < 4; i++)
            #pragma unroll
            for (int j = 0; j < 4; j++) sacc[i][j] = 0.f;
        #pragma unroll 8
        for (int d = 0; d < DHd; d++) {
            float qr[4], kr[4];
            #pragma unroll
            for (int i = 0; i < 4; i++) qr[i] = Qs[ty*4 + i][d];
            #pragma unroll
            for (int j = 0; j < 4; j++) kr[j] = Ks[tx*4 + j][d];
            #pragma unroll
            for (int i = 0; i < 4; i++)
                #pragma unroll
                for (int j = 0; j < 4; j++) sacc[i][j] += qr[i] * kr[j];
        }
        #pragma unroll
        for (int i = 0; i < 4; i++) {
            #pragma unroll
            for (int j = 0; j < 4; j++) {
                float sc = sacc[i][j] * 0.125f;   // 1/sqrt(64)
                if (band) {
                    int qi = q0 + ty*4 + i, ki = k0 + tx*4 + j;
                    int dlt = qi - ki; if (dlt < 0) dlt = -dlt;
                    sc += (dlt <= Rr) ? 1.0f : 0.0f;
                }
                Ps[ty*4 + i][tx*4 + j] = sc;
            }
        }
        __syncthreads();

        // online softmax row update (one thread per row)
        if (tid < AQ) {
            float mo = rm[tid], mx = mo;
            #pragma unroll 8
            for (int j = 0; j < AK; j++) mx = fmaxf(mx, Ps[tid][j]);
            float c = __expf(mo - mx);
            float sum = 0.f;
            #pragma unroll 8
            for (int j = 0; j < AK; j++) {
                float p = __expf(Ps[tid][j] - mx);
                Ps[tid][j] = p; sum += p;
            }
            rl[tid] = rl[tid] * c + sum;
            rm[tid] = mx; rc[tid] = c;
        }
        __syncthreads();

        // rescale O + accumulate P@V (4 q-rows x 8 dh-cols per thread)
        #pragma unroll
        for (int i = 0; i < 4; i++) {
            float ci = rc[ty*4 + i];
            #pragma unroll
            for (int j = 0; j < 8; j++) Oacc[i][j] *= ci;
        }
        #pragma unroll 4
        for (int kk = 0; kk < AK; kk++) {
            float p[4], vv[8];
            #pragma unroll
            for (int i = 0; i < 4; i++) p[i] = Ps[ty*4 + i][kk];
            #pragma unroll
            for (int j = 0; j < 8; j++) vv[j] = Vs[kk][tx*8 + j];
            #pragma unroll
            for (int i = 0; i < 4; i++)
                #pragma unroll
                for (int j = 0; j < 8; j++) Oacc[i][j] += p[i] * vv[j];
        }
    }

    float* ob = Op + ((long)b * Sq + q0) * Dd + h * DHd;
    #pragma unroll
    for (int i = 0; i < 4; i++) {
        int r = ty*4 + i;
        float inv = 1.0f / rl[r];
        #pragma unroll
        for (int j = 0; j < 8; j++)
            ob[(long)r * Dd + tx*8 + j] = Oacc[i][j] * inv;
    }
}

// ---------------- LayerNorm (row per block) ---------------------------------
__global__ __launch_bounds__(256)
void ln_kernel(const float* __restrict__ in, const float* __restrict__ g,
               const float* __restrict__ bta, float* __restrict__ out)
{
    const int row = blockIdx.x;
    const float* x = in + (long)row * Dd;
    float* o = out + (long)row * Dd;
    const int tid = threadIdx.x;

    float v0 = x[tid], v1 = x[tid + 256], v2 = x[tid + 512];
    float s = v0 + v1 + v2;

    __shared__ float sred[8];
    __shared__ float smean, svar;

    #pragma unroll
    for (int off = 16; off; off >>= 1) s += __shfl_xor_sync(0xffffffffu, s, off);
    if ((tid & 31) == 0) sred[tid >> 5] = s;
    __syncthreads();
    if (tid == 0) {
        float t = 0.f;
        #pragma unroll
        for (int i = 0; i < 8; i++) t += sred[i];
        smean = t * (1.0f / Dd);
    }
    __syncthreads();
    float m = smean;
    float d0 = v0 - m, d1 = v1 - m, d2 = v2 - m;
    float sq = d0*d0 + d1*d1 + d2*d2;
    #pragma unroll
    for (int off = 16; off; off >>= 1) sq += __shfl_xor_sync(0xffffffffu, sq, off);
    if ((tid & 31) == 0) sred[tid >> 5] = sq;
    __syncthreads();
    if (tid == 0) {
        float t = 0.f;
        #pragma unroll
        for (int i = 0; i < 8; i++) t += sred[i];
        svar = t * (1.0f / Dd);
    }
    __syncthreads();
    float inv = rsqrtf(svar + 1e-12f);
    o[tid      ] = d0 * inv * g[tid      ] + bta[tid      ];
    o[tid + 256] = d1 * inv * g[tid + 256] + bta[tid + 256];
    o[tid + 512] = d2 * inv * g[tid + 512] + bta[tid + 512];
}

// ---------------- launch ----------------------------------------------------
static inline void launch_gemm(int act, int res,
                               const float* A, const float* W, const float* bias,
                               const float* Rz, float* C, int M, int N, int K)
{
    dim3 g(N / GBN, (M + GBM - 1) / GBM);
    if (act == 0 && res == 0) gemm_kernel<0,0><<<g, 256>>>(A, W, bias, Rz, C, M, N, K);
    else if (act == 0)        gemm_kernel<0,1><<<g, 256>>>(A, W, bias, Rz, C, M, N, K);
    else if (res == 0)        gemm_kernel<1,0><<<g, 256>>>(A, W, bias, Rz, C, M, N, K);
    else                      gemm_kernel<1,1><<<g, 256>>>(A, W, bias, Rz, C, M, N, K);
}

extern "C" void kernel_launch(void* const* d_in, const int* in_sizes, int n_in,
                              void* d_out, int out_size)
{
    const float* X     = (const float*)d_in[0];
    const float* tag   = (const float*)d_in[1];
    const float* sa_wq = (const float*)d_in[2];  const float* sa_bq = (const float*)d_in[3];
    const float* sa_wk = (const float*)d_in[4];  const float* sa_bk = (const float*)d_in[5];
    const float* sa_wv = (const float*)d_in[6];  const float* sa_bv = (const float*)d_in[7];
    const float* sa_wo = (const float*)d_in[8];  const float* sa_bo = (const float*)d_in[9];
    const float* sa_lg = (const float*)d_in[10]; const float* sa_lb = (const float*)d_in[11];
    const float* ca_wq = (const float*)d_in[12]; const float* ca_bq = (const float*)d_in[13];
    const float* ca_wk = (const float*)d_in[14]; const float* ca_bk = (const float*)d_in[15];
    const float* ca_wv = (const float*)d_in[16]; const float* ca_bv = (const float*)d_in[17];
    const float* ca_wo = (const float*)d_in[18]; const float* ca_bo = (const float*)d_in[19];
    const float* ca_lg = (const float*)d_in[20]; const float* ca_lb = (const float*)d_in[21];
    const float* ff_w1 = (const float*)d_in[22]; const float* ff_b1 = (const float*)d_in[23];
    const float* ff_w2 = (const float*)d_in[24]; const float* ff_b2 = (const float*)d_in[25];
    const float* ff_lg = (const float*)d_in[26]; const float* ff_lb = (const float*)d_in[27];
    float* out = (float*)d_out;

    float *q, *k, *v, *ctx, *t1, *x1, *x2, *ck, *cv, *ff;
    cudaGetSymbolAddress((void**)&q,   g_q);
    cudaGetSymbolAddress((void**)&k,   g_k);
    cudaGetSymbolAddress((void**)&v,   g_v);
    cudaGetSymbolAddress((void**)&ctx, g_ctx);
    cudaGetSymbolAddress((void**)&t1,  g_t1);
    cudaGetSymbolAddress((void**)&x1,  g_x1);
    cudaGetSymbolAddress((void**)&x2,  g_x2);
    cudaGetSymbolAddress((void**)&ck,  g_ck);
    cudaGetSymbolAddress((void**)&cv,  g_cv);
    cudaGetSymbolAddress((void**)&ff,  g_ff);

    const int M = Bb * Ss;                 // 4096
    dim3 agrid(Ss / AQ, Hh, Bb);           // (32, 12, 2)

    // ---- self-attention ----
    launch_gemm(0, 0, X, sa_wq, sa_bq, nullptr, q, M, Dd, Dd);
    launch_gemm(0, 0, X, sa_wk, sa_bk, nullptr, k, M, Dd, Dd);
    launch_gemm(0, 0, X, sa_wv, sa_bv, nullptr, v, M, Dd, Dd);
    attn_kernel<<<agrid, 128>>>(q, k, v, ctx, Ss, Ss, (long)Ss * Dd, 1);
    launch_gemm(0, 1, ctx, sa_wo, sa_bo, X, t1, M, Dd, Dd);
    ln_kernel<<<M, 256>>>(t1, sa_lg, sa_lb, x1);

    // ---- cross-attention (keys/values from 64 tag embeddings, batch-shared) ----
    launch_gemm(0, 0, x1, ca_wq, ca_bq, nullptr, q, M, Dd, Dd);
    launch_gemm(0, 0, tag, ca_wk, ca_bk, nullptr, ck, Tt, Dd, Dd);
    launch_gemm(0, 0, tag, ca_wv, ca_bv, nullptr, cv, Tt, Dd, Dd);
    attn_kernel<<<agrid, 128>>>(q, ck, cv, ctx, Ss, Tt, 0L, 0);
    launch_gemm(0, 1, ctx, ca_wo, ca_bo, x1, t1, M, Dd, Dd);
    ln_kernel<<<M, 256>>>(t1, ca_lg, ca_lb, x2);

    // ---- FFN ----
    launch_gemm(1, 0, x2, ff_w1, ff_b1, nullptr, ff, M, FFd, Dd);
    launch_gemm(0, 1, ff, ff_w2, ff_b2, x2, t1, M, Dd, FFd);
    ln_kernel<<<M, 256>>>(t1, ff_lg, ff_lb, out);
}

// round 6
// speedup vs baseline: 1.1732x; 1.1732x over previous
#include <cuda_runtime.h>
#include <cuda_bf16.h>
#include <math.h>
#include <cstdint>

// Problem constants
#define Bb   2
#define Ss   2048
#define Dd   768
#define Hh   12
#define DHd  64
#define Tt   64
#define FFd  3072
#define Rr   50

// ---------------- scratch (device globals; no allocations allowed) ----------
__device__ float g_q  [Bb*Ss*Dd];
__device__ float g_k  [Bb*Ss*Dd];
__device__ float g_v  [Bb*Ss*Dd];
__device__ float g_ctx[Bb*Ss*Dd];
__device__ float g_t1 [Bb*Ss*Dd];
__device__ float g_x1 [Bb*Ss*Dd];
__device__ float g_x2 [Bb*Ss*Dd];
__device__ float g_ck [Tt*Dd];
__device__ float g_cv [Tt*Dd];
__device__ float g_ff [Bb*Ss*FFd];

// =============== warp-level bf16 MMA (HMMA path, compiles on sm_103) ========
__device__ __forceinline__ void mma16816(float* c, const uint32_t* a, const uint32_t* b) {
    asm volatile(
        "mma.sync.aligned.m16n8k16.row.col.f32.bf16.bf16.f32 "
        "{%0,%1,%2,%3}, {%4,%5,%6,%7}, {%8,%9}, {%0,%1,%2,%3};\n"
        : "+f"(c[0]), "+f"(c[1]), "+f"(c[2]), "+f"(c[3])
        : "r"(a[0]), "r"(a[1]), "r"(a[2]), "r"(a[3]), "r"(b[0]), "r"(b[1]));
}

__device__ __forceinline__ uint32_t pack_bf2(__nv_bfloat16 a, __nv_bfloat16 b) {
    return ((uint32_t)__bfloat16_as_ushort(b) << 16) | (uint32_t)__bfloat16_as_ushort(a);
}

// ======== split-bf16 tensor-core GEMM: C = act(A[M,K]@W[K,N] + bias (+res)) =
// CTA tile 128x128, BK=32, 256 threads (8 warps), warp tile 64x32.
// x = hi + lo (two bf16); A@B ~= Ah@Bh + Al@Bh + Ah@Bl  (3 MMAs, ~2^-17 err)
#define BKc 32
#define LDS_STR 40   // bf16 elems per smem row (80B)

template<int ACT, int RES>
__global__ void __launch_bounds__(256)
gemm_mma(const float* __restrict__ A, const float* __restrict__ W,
         const float* __restrict__ bias, const float* __restrict__ Rz,
         float* __restrict__ C, int M, int N, int K)
{
    __shared__ __nv_bfloat16 Ah[128][LDS_STR];
    __shared__ __nv_bfloat16 Al[128][LDS_STR];
    __shared__ __nv_bfloat16 Bh[128][LDS_STR];   // [n][k]
    __shared__ __nv_bfloat16 Bl[128][LDS_STR];

    const int tid  = threadIdx.x;
    const int wid  = tid >> 5;
    const int lane = tid & 31;
    const int wm   = (wid & 1) * 64;      // warp m offset in tile
    const int wn   = (wid >> 1) * 32;     // warp n offset in tile
    const int bm   = blockIdx.y * 128;
    const int bn   = blockIdx.x * 128;
    const int nch  = K / BKc;

    const int gq = lane >> 2;             // group id 0..7 (row/col within frag)
    const int gt = lane & 3;              // thread-in-group 0..3

    float acc[4][4][4];
    #pragma unroll
    for (int i = 0; i < 4; i++)
        #pragma unroll
        for (int j = 0; j < 4; j++)
            #pragma unroll
            for (int e = 0; e < 4; e++) acc[i][j][e] = 0.f;

    // staging registers (software pipeline)
    // A: 128 rows x 32 k. 2 threads/row, each 4 float4 (16 floats).
    const int ar  = tid >> 1;                  // row 0..127
    const int ac4 = (tid & 1) * 4;             // float4 index base {0,4}
    // B: 32 k-rows x 128 n. 8 threads/k-row, each 4 consecutive float4.
    const int bk  = tid >> 3;                  // k row 0..31
    const int bn0 = (tid & 7) * 16;            // n start (16 floats)

    float4 Ast[4], Bst[4];

    // prologue: load chunk 0
    {
        const float* Ab = A + (long)(bm + ar) * K;
        #pragma unroll
        for (int u = 0; u < 4; u++)
            Ast[u] = (bm + ar < M) ? *(const float4*)(Ab + (ac4 + u) * 4)
                                   : make_float4(0.f,0.f,0.f,0.f);
        const float* Wb = W + (long)bk * N + bn + bn0;
        #pragma unroll
        for (int u = 0; u < 4; u++)
            Bst[u] = *(const float4*)(Wb + u * 4);
    }

    for (int c = 0; c < nch; c++) {
        // ---- convert staged regs -> smem (hi/lo split) ----
        #pragma unroll
        for (int u = 0; u < 4; u++) {
            float4 v = Ast[u];
            __nv_bfloat16 h0 = __float2bfloat16(v.x), h1 = __float2bfloat16(v.y);
            __nv_bfloat16 h2 = __float2bfloat16(v.z), h3 = __float2bfloat16(v.w);
            __nv_bfloat16 l0 = __float2bfloat16(v.x - __bfloat162float(h0));
            __nv_bfloat16 l1 = __float2bfloat16(v.y - __bfloat162float(h1));
            __nv_bfloat16 l2 = __float2bfloat16(v.z - __bfloat162float(h2));
            __nv_bfloat16 l3 = __float2bfloat16(v.w - __bfloat162float(h3));
            uint32_t* ph = (uint32_t*)&Ah[ar][(ac4 + u) * 4];
            uint32_t* pl = (uint32_t*)&Al[ar][(ac4 + u) * 4];
            ph[0] = pack_bf2(h0, h1); ph[1] = pack_bf2(h2, h3);
            pl[0] = pack_bf2(l0, l1); pl[1] = pack_bf2(l2, l3);
        }
        #pragma unroll
        for (int u = 0; u < 4; u++) {
            float4 v = Bst[u];
            const float* vv = (const float*)&v;
            #pragma unroll
            for (int e = 0; e < 4; e++) {
                __nv_bfloat16 h = __float2bfloat16(vv[e]);
                __nv_bfloat16 l = __float2bfloat16(vv[e] - __bfloat162float(h));
                Bh[bn0 + u * 4 + e][bk] = h;
                Bl[bn0 + u * 4 + e][bk] = l;
            }
        }
        __syncthreads();

        // ---- prefetch chunk c+1 ----
        if (c + 1 < nch) {
            const int k0 = (c + 1) * BKc;
            const float* Ab = A + (long)(bm + ar) * K + k0;
            #pragma unroll
            for (int u = 0; u < 4; u++)
                Ast[u] = (bm + ar < M) ? *(const float4*)(Ab + (ac4 + u) * 4)
                                       : make_float4(0.f,0.f,0.f,0.f);
            const float* Wb = W + (long)(k0 + bk) * N + bn + bn0;
            #pragma unroll
            for (int u = 0; u < 4; u++)
                Bst[u] = *(const float4*)(Wb + u * 4);
        }

        // ---- MMAs over this chunk (2 k16 steps) ----
        #pragma unroll
        for (int ks = 0; ks < 2; ks++) {
            const int kk = ks * 16 + gt * 2;
            uint32_t bhf[4][2], blf[4][2];
            #pragma unroll
            for (int j = 0; j < 4; j++) {
                int nr = wn + j * 8 + gq;
                bhf[j][0] = *(const uint32_t*)&Bh[nr][kk];
                bhf[j][1] = *(const uint32_t*)&Bh[nr][kk + 8];
                blf[j][0] = *(const uint32_t*)&Bl[nr][kk];
                blf[j][1] = *(const uint32_t*)&Bl[nr][kk + 8];
            }
            #pragma unroll
            for (int i = 0; i < 4; i++) {
                int r0 = wm + i * 16 + gq;
                uint32_t ahf[4], alf[4];
                ahf[0] = *(const uint32_t*)&Ah[r0    ][kk];
                ahf[1] = *(const uint32_t*)&Ah[r0 + 8][kk];
                ahf[2] = *(const uint32_t*)&Ah[r0    ][kk + 8];
                ahf[3] = *(const uint32_t*)&Ah[r0 + 8][kk + 8];
                alf[0] = *(const uint32_t*)&Al[r0    ][kk];
                alf[1] = *(const uint32_t*)&Al[r0 + 8][kk];
                alf[2] = *(const uint32_t*)&Al[r0    ][kk + 8];
                alf[3] = *(const uint32_t*)&Al[r0 + 8][kk + 8];
                #pragma unroll
                for (int j = 0; j < 4; j++) {
                    mma16816(acc[i][j], ahf, bhf[j]);
                    mma16816(acc[i][j], alf, bhf[j]);
                    mma16816(acc[i][j], ahf, blf[j]);
                }
            }
        }
        __syncthreads();
    }

    // ---- epilogue ----
    #pragma unroll
    for (int i = 0; i < 4; i++) {
        #pragma unroll
        for (int rr = 0; rr < 2; rr++) {
            int m = bm + wm + i * 16 + gq + rr * 8;
            if (m >= M) continue;
            #pragma unroll
            for (int j = 0; j < 4; j++) {
                int n = bn + wn + j * 8 + gt * 2;
                float v0 = acc[i][j][rr * 2 + 0] + bias[n];
                float v1 = acc[i][j][rr * 2 + 1] + bias[n + 1];
                if (RES) {
                    const float* rp = Rz + (long)m * N + n;
                    v0 += rp[0]; v1 += rp[1];
                }
                if (ACT) {
                    v0 = 0.5f * v0 * (1.0f + erff(v0 * 0.70710678118654752f));
                    v1 = 0.5f * v1 * (1.0f + erff(v1 * 0.70710678118654752f));
                }
                *(float2*)(C + (long)m * N + n) = make_float2(v0, v1);
            }
        }
    }
}

// ---------------- attention (flash-style, fp32) -----------------------------
#define AQ 64
#define AK 32

__global__ __launch_bounds__(128)
void attn_kernel(const float* __restrict__ Qp, const float* __restrict__ Kp,
                 const float* __restrict__ Vp, float* __restrict__ Op,
                 int Sq, int Sk, long kvbs, int band)
{
    __shared__ float Qs[AQ][DHd + 1];
    __shared__ float Ks[AK][DHd + 1];
    __shared__ float Vs[AK][DHd + 1];
    __shared__ float Ps[AQ][AK + 1];
    __shared__ float rm[AQ], rl[AQ], rc[AQ];

    const int b  = blockIdx.z;
    const int h  = blockIdx.y;
    const int q0 = blockIdx.x * AQ;
    const int tid = threadIdx.x;
    const int tx = tid & 7;
    const int ty = tid >> 3;

    const float* qb = Qp + ((long)b * Sq) * Dd + h * DHd;
    const float* kb = Kp + (long)b * kvbs + h * DHd;
    const float* vb = Vp + (long)b * kvbs + h * DHd;

    for (int i = tid; i < AQ * DHd; i += 128)
        Qs[i >> 6][i & 63] = qb[(long)(q0 + (i >> 6)) * Dd + (i & 63)];
    if (tid < AQ) { rm[tid] = -1e30f; rl[tid] = 0.f; }

    float Oacc[4][8];
    #pragma unroll
    for (int i = 0; i < 4; i++)
        #pragma unroll
        for (int j = 0; j < 8; j++) Oacc[i][j] = 0.f;

    const int ntiles = Sk / AK;
    for (int kt = 0; kt < ntiles; kt++) {
        const int k0 = kt * AK;
        __syncthreads();
        for (int i = tid; i < AK * DHd; i += 128) {
            int r = i >> 6, c = i & 63;
            Ks[r][c] = kb[(long)(k0 + r) * Dd + c];
            Vs[r][c] = vb[(long)(k0 + r) * Dd + c];
        }
        __syncthreads();

        float sacc[4][4];
        #pragma unroll
        for (int i = 0; i < 4; i++)
            #pragma unroll
            for (int j = 0; j < 4; j++) sacc[i][j] = 0.f;
        #pragma unroll 8
        for (int d = 0; d < DHd; d++) {
            float qr[4], kr[4];
            #pragma unroll
            for (int i = 0; i < 4; i++) qr[i] = Qs[ty*4 + i][d];
            #pragma unroll
            for (int j = 0; j < 4; j++) kr[j] = Ks[tx*4 + j][d];
            #pragma unroll
            for (int i = 0; i < 4; i++)
                #pragma unroll
                for (int j = 0; j < 4; j++) sacc[i][j] += qr[i] * kr[j];
        }
        #pragma unroll
        for (int i = 0; i < 4; i++) {
            #pragma unroll
            for (int j = 0; j < 4; j++) {
                float sc = sacc[i][j] * 0.125f;
                if (band) {
                    int qi = q0 + ty*4 + i, ki = k0 + tx*4 + j;
                    int dlt = qi - ki; if (dlt < 0) dlt = -dlt;
                    sc += (dlt <= Rr) ? 1.0f : 0.0f;
                }
                Ps[ty*4 + i][tx*4 + j] = sc;
            }
        }
        __syncthreads();

        if (tid < AQ) {
            float mo = rm[tid], mx = mo;
            #pragma unroll 8
            for (int j = 0; j < AK; j++) mx = fmaxf(mx, Ps[tid][j]);
            float cc = __expf(mo - mx);
            float sum = 0.f;
            #pragma unroll 8
            for (int j = 0; j < AK; j++) {
                float p = __expf(Ps[tid][j] - mx);
                Ps[tid][j] = p; sum += p;
            }
            rl[tid] = rl[tid] * cc + sum;
            rm[tid] = mx; rc[tid] = cc;
        }
        __syncthreads();

        #pragma unroll
        for (int i = 0; i < 4; i++) {
            float ci = rc[ty*4 + i];
            #pragma unroll
            for (int j = 0; j < 8; j++) Oacc[i][j] *= ci;
        }
        #pragma unroll 4
        for (int kk = 0; kk < AK; kk++) {
            float p[4], vv[8];
            #pragma unroll
            for (int i = 0; i < 4; i++) p[i] = Ps[ty*4 + i][kk];
            #pragma unroll
            for (int j = 0; j < 8; j++) vv[j] = Vs[kk][tx*8 + j];
            #pragma unroll
            for (int i = 0; i < 4; i++)
                #pragma unroll
                for (int j = 0; j < 8; j++) Oacc[i][j] += p[i] * vv[j];
        }
    }

    float* ob = Op + ((long)b * Sq + q0) * Dd + h * DHd;
    #pragma unroll
    for (int i = 0; i < 4; i++) {
        int r = ty*4 + i;
        float inv = 1.0f / rl[r];
        #pragma unroll
        for (int j = 0; j < 8; j++)
            ob[(long)r * Dd + tx*8 + j] = Oacc[i][j] * inv;
    }
}

// ---------------- LayerNorm (row per block) ---------------------------------
__global__ __launch_bounds__(256)
void ln_kernel(const float* __restrict__ in, const float* __restrict__ g,
               const float* __restrict__ bta, float* __restrict__ out)
{
    const int row = blockIdx.x;
    const float* x = in + (long)row * Dd;
    float* o = out + (long)row * Dd;
    const int tid = threadIdx.x;

    float v0 = x[tid], v1 = x[tid + 256], v2 = x[tid + 512];
    float s = v0 + v1 + v2;

    __shared__ float sred[8];
    __shared__ float smean, svar;

    #pragma unroll
    for (int off = 16; off; off >>= 1) s += __shfl_xor_sync(0xffffffffu, s, off);
    if ((tid & 31) == 0) sred[tid >> 5] = s;
    __syncthreads();
    if (tid == 0) {
        float t = 0.f;
        #pragma unroll
        for (int i = 0; i < 8; i++) t += sred[i];
        smean = t * (1.0f / Dd);
    }
    __syncthreads();
    float m = smean;
    float d0 = v0 - m, d1 = v1 - m, d2 = v2 - m;
    float sq = d0*d0 + d1*d1 + d2*d2;
    #pragma unroll
    for (int off = 16; off; off >>= 1) sq += __shfl_xor_sync(0xffffffffu, sq, off);
    if ((tid & 31) == 0) sred[tid >> 5] = sq;
    __syncthreads();
    if (tid == 0) {
        float t = 0.f;
        #pragma unroll
        for (int i = 0; i < 8; i++) t += sred[i];
        svar = t * (1.0f / Dd);
    }
    __syncthreads();
    float inv = rsqrtf(svar + 1e-12f);
    o[tid      ] = d0 * inv * g[tid      ] + bta[tid      ];
    o[tid + 256] = d1 * inv * g[tid + 256] + bta[tid + 256];
    o[tid + 512] = d2 * inv * g[tid + 512] + bta[tid + 512];
}

// ---------------- launch ----------------------------------------------------
static inline void launch_gemm(int act, int res,
                               const float* A, const float* W, const float* bias,
                               const float* Rz, float* C, int M, int N, int K)
{
    dim3 g(N / 128, (M + 127) / 128);
    if (act == 0 && res == 0) gemm_mma<0,0><<<g, 256>>>(A, W, bias, Rz, C, M, N, K);
    else if (act == 0)        gemm_mma<0,1><<<g, 256>>>(A, W, bias, Rz, C, M, N, K);
    else                      gemm_mma<1,0><<<g, 256>>>(A, W, bias, Rz, C, M, N, K);
}

extern "C" void kernel_launch(void* const* d_in, const int* in_sizes, int n_in,
                              void* d_out, int out_size)
{
    const float* X     = (const float*)d_in[0];
    const float* tag   = (const float*)d_in[1];
    const float* sa_wq = (const float*)d_in[2];  const float* sa_bq = (const float*)d_in[3];
    const float* sa_wk = (const float*)d_in[4];  const float* sa_bk = (const float*)d_in[5];
    const float* sa_wv = (const float*)d_in[6];  const float* sa_bv = (const float*)d_in[7];
    const float* sa_wo = (const float*)d_in[8];  const float* sa_bo = (const float*)d_in[9];
    const float* sa_lg = (const float*)d_in[10]; const float* sa_lb = (const float*)d_in[11];
    const float* ca_wq = (const float*)d_in[12]; const float* ca_bq = (const float*)d_in[13];
    const float* ca_wk = (const float*)d_in[14]; const float* ca_bk = (const float*)d_in[15];
    const float* ca_wv = (const float*)d_in[16]; const float* ca_bv = (const float*)d_in[17];
    const float* ca_wo = (const float*)d_in[18]; const float* ca_bo = (const float*)d_in[19];
    const float* ca_lg = (const float*)d_in[20]; const float* ca_lb = (const float*)d_in[21];
    const float* ff_w1 = (const float*)d_in[22]; const float* ff_b1 = (const float*)d_in[23];
    const float* ff_w2 = (const float*)d_in[24]; const float* ff_b2 = (const float*)d_in[25];
    const float* ff_lg = (const float*)d_in[26]; const float* ff_lb = (const float*)d_in[27];
    float* out = (float*)d_out;

    float *q, *k, *v, *ctx, *t1, *x1, *x2, *ck, *cv, *ff;
    cudaGetSymbolAddress((void**)&q,   g_q);
    cudaGetSymbolAddress((void**)&k,   g_k);
    cudaGetSymbolAddress((void**)&v,   g_v);
    cudaGetSymbolAddress((void**)&ctx, g_ctx);
    cudaGetSymbolAddress((void**)&t1,  g_t1);
    cudaGetSymbolAddress((void**)&x1,  g_x1);
    cudaGetSymbolAddress((void**)&x2,  g_x2);
    cudaGetSymbolAddress((void**)&ck,  g_ck);
    cudaGetSymbolAddress((void**)&cv,  g_cv);
    cudaGetSymbolAddress((void**)&ff,  g_ff);

    const int M = Bb * Ss;                 // 4096
    dim3 agrid(Ss / AQ, Hh, Bb);

    // ---- self-attention ----
    launch_gemm(0, 0, X, sa_wq, sa_bq, nullptr, q, M, Dd, Dd);
    launch_gemm(0, 0, X, sa_wk, sa_bk, nullptr, k, M, Dd, Dd);
    launch_gemm(0, 0, X, sa_wv, sa_bv, nullptr, v, M, Dd, Dd);
    attn_kernel<<<agrid, 128>>>(q, k, v, ctx, Ss, Ss, (long)Ss * Dd, 1);
    launch_gemm(0, 1, ctx, sa_wo, sa_bo, X, t1, M, Dd, Dd);
    ln_kernel<<<M, 256>>>(t1, sa_lg, sa_lb, x1);

    // ---- cross-attention (keys/values from 64 tag embeddings) ----
    launch_gemm(0, 0, x1, ca_wq, ca_bq, nullptr, q, M, Dd, Dd);
    launch_gemm(0, 0, tag, ca_wk, ca_bk, nullptr, ck, Tt, Dd, Dd);
    launch_gemm(0, 0, tag, ca_wv, ca_bv, nullptr, cv, Tt, Dd, Dd);
    attn_kernel<<<agrid, 128>>>(q, ck, cv, ctx, Ss, Tt, 0L, 0);
    launch_gemm(0, 1, ctx, ca_wo, ca_bo, x1, t1, M, Dd, Dd);
    ln_kernel<<<M, 256>>>(t1, ca_lg, ca_lb, x2);

    // ---- FFN ----
    launch_gemm(1, 0, x2, ff_w1, ff_b1, nullptr, ff, M, FFd, Dd);
    launch_gemm(0, 1, ff, ff_w2, ff_b2, x2, t1, M, Dd, FFd);
    ln_kernel<<<M, 256>>>(t1, ff_lg, ff_lb, out);
}

// round 7
// speedup vs baseline: 1.6799x; 1.4319x over previous
#include <cuda_runtime.h>
#include <cuda_bf16.h>
#include <math.h>
#include <cstdint>

// Problem constants
#define Bb   2
#define Ss   2048
#define Dd   768
#define Hh   12
#define DHd  64
#define Tt   64
#define FFd  3072
#define Rr   50

#define MTOT (Bb*Ss)        // 4096

// ---------------- scratch (device globals; no allocations allowed) ----------
__device__ float g_q  [MTOT*Dd];
__device__ float g_k  [MTOT*Dd];
__device__ float g_v  [MTOT*Dd];
__device__ float g_t1 [MTOT*Dd];
__device__ float g_x1 [MTOT*Dd];
__device__ float g_x2 [MTOT*Dd];
__device__ float g_ck [Tt*Dd];
__device__ float g_cv [Tt*Dd];

// bf16 hi/lo activation buffers
__device__ __nv_bfloat16 g_xh [MTOT*Dd],  g_xl [MTOT*Dd];
__device__ __nv_bfloat16 g_x1h[MTOT*Dd],  g_x1l[MTOT*Dd];
__device__ __nv_bfloat16 g_x2h[MTOT*Dd],  g_x2l[MTOT*Dd];
__device__ __nv_bfloat16 g_cth[MTOT*Dd],  g_ctl[MTOT*Dd];
__device__ __nv_bfloat16 g_ffh[MTOT*FFd], g_ffl[MTOT*FFd];
__device__ __nv_bfloat16 g_tgh[Tt*Dd],    g_tgl[Tt*Dd];

// transposed weights [N][K] hi/lo: 8x(768x768) + 768x3072 + 3072x768
#define WSZ  (Dd*Dd)                 // 589824
#define WOFF_FF1 (8*WSZ)             // 4718592
#define WOFF_FF2 (WOFF_FF1 + Dd*FFd) // 7077888
#define WTOT (WOFF_FF2 + FFd*Dd)     // 9437184
__device__ __nv_bfloat16 g_wh[WTOT], g_wl[WTOT];

// =============== helpers =====================================================
__device__ __forceinline__ void mma16816(float* c, const uint32_t* a, const uint32_t* b) {
    asm volatile(
        "mma.sync.aligned.m16n8k16.row.col.f32.bf16.bf16.f32 "
        "{%0,%1,%2,%3}, {%4,%5,%6,%7}, {%8,%9}, {%0,%1,%2,%3};\n"
        : "+f"(c[0]), "+f"(c[1]), "+f"(c[2]), "+f"(c[3])
        : "r"(a[0]), "r"(a[1]), "r"(a[2]), "r"(a[3]), "r"(b[0]), "r"(b[1]));
}
__device__ __forceinline__ uint32_t pack_bf2(__nv_bfloat16 a, __nv_bfloat16 b) {
    return ((uint32_t)__bfloat16_as_ushort(b) << 16) | (uint32_t)__bfloat16_as_ushort(a);
}
__device__ __forceinline__ uint32_t smem_u32(const void* p) {
    uint32_t a;
    asm("{ .reg .u64 t; cvta.to.shared.u64 t, %1; cvt.u32.u64 %0, t; }" : "=r"(a) : "l"(p));
    return a;
}
__device__ __forceinline__ void cpa16(uint32_t dst, const void* src, bool valid) {
    int sz = valid ? 16 : 0;
    asm volatile("cp.async.cg.shared.global [%0], [%1], 16, %2;"
                 :: "r"(dst), "l"(src), "r"(sz));
}
#define CP_COMMIT() asm volatile("cp.async.commit_group;" ::: "memory")
#define CP_WAIT(n)  asm volatile("cp.async.wait_group %0;" :: "n"(n) : "memory")

__device__ __forceinline__ void split_bf(float v, __nv_bfloat16& h, __nv_bfloat16& l) {
    h = __float2bfloat16(v);
    l = __float2bfloat16(v - __bfloat162float(h));
}

// ============ conversion kernels ============================================
__global__ void fconv(const float* __restrict__ x, __nv_bfloat16* __restrict__ h,
                      __nv_bfloat16* __restrict__ l, int n4)
{
    int i = blockIdx.x * 256 + threadIdx.x;
    if (i >= n4) return;
    float4 v = ((const float4*)x)[i];
    __nv_bfloat16 h0,h1,h2,h3,l0,l1,l2,l3;
    split_bf(v.x,h0,l0); split_bf(v.y,h1,l1); split_bf(v.z,h2,l2); split_bf(v.w,h3,l3);
    ((uint2*)h)[i] = make_uint2(pack_bf2(h0,h1), pack_bf2(h2,h3));
    ((uint2*)l)[i] = make_uint2(pack_bf2(l0,l1), pack_bf2(l2,l3));
}

// W[K][N] fp32 -> Wh/Wl[N][K] bf16 (transpose + split)
__global__ void wtconv(const float* __restrict__ W, __nv_bfloat16* __restrict__ Wh,
                       __nv_bfloat16* __restrict__ Wl, int K, int N)
{
    __shared__ float t[32][33];
    const int k0 = blockIdx.y * 32, n0 = blockIdx.x * 32;
    const int tx = threadIdx.x, ty = threadIdx.y;   // 32 x 8
    #pragma unroll
    for (int i = 0; i < 4; i++)
        t[ty + i*8][tx] = W[(long)(k0 + ty + i*8) * N + n0 + tx];
    __syncthreads();
    #pragma unroll
    for (int i = 0; i < 4; i++) {
        int n = n0 + ty + i*8;
        float v = t[tx][ty + i*8];
        __nv_bfloat16 h, l; split_bf(v, h, l);
        Wh[(long)n * K + k0 + tx] = h;
        Wl[(long)n * K + k0 + tx] = l;
    }
}

// ======== split-bf16 tensor-core GEMM (pre-converted operands) ===============
// C = act(A@W + bias (+res)); A: hi/lo [M][K] bf16; B: hi/lo [N][K] bf16.
// CTA 128x128, BK=32, 256 thr, double-buffered cp.async.
#define STG_B 40960   // 4 arrays * 128 rows * 40 elems * 2B

template<int ACT, int RES, int WF32, int WBF>
__global__ void __launch_bounds__(256)
gemm_bf(const __nv_bfloat16* __restrict__ Ahp, const __nv_bfloat16* __restrict__ Alp,
        const __nv_bfloat16* __restrict__ Bhp, const __nv_bfloat16* __restrict__ Blp,
        const float* __restrict__ bias, const float* __restrict__ Rz,
        float* __restrict__ C, __nv_bfloat16* __restrict__ Chp, __nv_bfloat16* __restrict__ Clp,
        int M, int N, int K)
{
    extern __shared__ char smem[];
    const uint32_t sb = smem_u32(smem);
    const int tid  = threadIdx.x;
    const int wid  = tid >> 5;
    const int lane = tid & 31;
    const int wm   = (wid & 1) * 64;
    const int wn   = (wid >> 1) * 32;
    const int bm   = blockIdx.y * 128;
    const int bn   = blockIdx.x * 128;
    const int nch  = K >> 5;
    const int gq = lane >> 2;
    const int gt = lane & 3;

    float acc[4][4][4];
    #pragma unroll
    for (int i = 0; i < 4; i++)
        #pragma unroll
        for (int j = 0; j < 4; j++)
            #pragma unroll
            for (int e = 0; e < 4; e++) acc[i][j][e] = 0.f;

    const __nv_bfloat16* srcs[4] = {Ahp, Alp, Bhp, Blp};

    // one stage = {Ah, Al, Bh, Bl}, each 128 rows x 32 bf16, row stride 40 elems (80B)
    auto load_stage = [&](int s, int k0) {
        #pragma unroll
        for (int a = 0; a < 4; a++) {
            #pragma unroll
            for (int t = 0; t < 2; t++) {
                int q   = tid + t * 256;        // 0..511
                int row = q >> 2, c4 = q & 3;
                int grow = (a < 2) ? (bm + row) : (bn + row);
                bool valid = (a < 2) ? (grow < M) : true;
                const __nv_bfloat16* src = srcs[a] + (long)(valid ? grow : 0) * K + k0 + c4 * 8;
                cpa16(sb + s * STG_B + a * 10240 + row * 80 + c4 * 16, src, valid);
            }
        }
    };

    load_stage(0, 0);
    CP_COMMIT();

    for (int c = 0; c < nch; c++) {
        if (c + 1 < nch) { load_stage((c + 1) & 1, (c + 1) * 32); CP_COMMIT(); CP_WAIT(1); }
        else             { CP_WAIT(0); }
        __syncthreads();

        const char* st = smem + (c & 1) * STG_B;
        const char* sAh = st;
        const char* sAl = st + 10240;
        const char* sBh = st + 20480;
        const char* sBl = st + 30720;

        #pragma unroll
        for (int ks = 0; ks < 2; ks++) {
            const int kk = ks * 16 + gt * 2;     // bf16 col; byte off = kk*2
            uint32_t bhf[4][2], blf[4][2];
            #pragma unroll
            for (int j = 0; j < 4; j++) {
                int nr = wn + j * 8 + gq;
                bhf[j][0] = *(const uint32_t*)(sBh + nr * 80 + kk * 2);
                bhf[j][1] = *(const uint32_t*)(sBh + nr * 80 + (kk + 8) * 2);
                blf[j][0] = *(const uint32_t*)(sBl + nr * 80 + kk * 2);
                blf[j][1] = *(const uint32_t*)(sBl + nr * 80 + (kk + 8) * 2);
            }
            #pragma unroll
            for (int i = 0; i < 4; i++) {
                int r0 = wm + i * 16 + gq;
                uint32_t ahf[4], alf[4];
                ahf[0] = *(const uint32_t*)(sAh + r0 * 80 + kk * 2);
                ahf[1] = *(const uint32_t*)(sAh + (r0 + 8) * 80 + kk * 2);
                ahf[2] = *(const uint32_t*)(sAh + r0 * 80 + (kk + 8) * 2);
                ahf[3] = *(const uint32_t*)(sAh + (r0 + 8) * 80 + (kk + 8) * 2);
                alf[0] = *(const uint32_t*)(sAl + r0 * 80 + kk * 2);
                alf[1] = *(const uint32_t*)(sAl + (r0 + 8) * 80 + kk * 2);
                alf[2] = *(const uint32_t*)(sAl + r0 * 80 + (kk + 8) * 2);
                alf[3] = *(const uint32_t*)(sAl + (r0 + 8) * 80 + (kk + 8) * 2);
                #pragma unroll
                for (int j = 0; j < 4; j++) {
                    mma16816(acc[i][j], ahf, bhf[j]);
                    mma16816(acc[i][j], alf, bhf[j]);
                    mma16816(acc[i][j], ahf, blf[j]);
                }
            }
        }
        __syncthreads();
    }

    // ---- epilogue ----
    #pragma unroll
    for (int i = 0; i < 4; i++) {
        #pragma unroll
        for (int rr = 0; rr < 2; rr++) {
            int m = bm + wm + i * 16 + gq + rr * 8;
            if (m >= M) continue;
            #pragma unroll
            for (int j = 0; j < 4; j++) {
                int n = bn + wn + j * 8 + gt * 2;
                float v0 = acc[i][j][rr * 2 + 0] + __ldg(&bias[n]);
                float v1 = acc[i][j][rr * 2 + 1] + __ldg(&bias[n + 1]);
                if (RES) {
                    const float* rp = Rz + (long)m * N + n;
                    v0 += rp[0]; v1 += rp[1];
                }
                if (ACT) {
                    v0 = 0.5f * v0 * (1.0f + erff(v0 * 0.70710678118654752f));
                    v1 = 0.5f * v1 * (1.0f + erff(v1 * 0.70710678118654752f));
                }
                if (WF32)
                    *(float2*)(C + (long)m * N + n) = make_float2(v0, v1);
                if (WBF) {
                    __nv_bfloat16 h0,h1,l0,l1;
                    split_bf(v0,h0,l0); split_bf(v1,h1,l1);
                    *(uint32_t*)(Chp + (long)m * N + n) = pack_bf2(h0,h1);
                    *(uint32_t*)(Clp + (long)m * N + n) = pack_bf2(l0,l1);
                }
            }
        }
    }
}

// ---------------- attention (flash-style fp32, bf16 hi/lo output) -----------
#define AQ 64
#define AK 32

__global__ __launch_bounds__(128)
void attn_kernel(const float* __restrict__ Qp, const float* __restrict__ Kp,
                 const float* __restrict__ Vp,
                 __nv_bfloat16* __restrict__ Ohp, __nv_bfloat16* __restrict__ Olp,
                 int Sq, int Sk, long kvbs, int band)
{
    __shared__ float Qs[AQ][DHd + 1];
    __shared__ float Ks[AK][DHd + 1];
    __shared__ float Vs[AK][DHd + 1];
    __shared__ float Ps[AQ][AK + 1];
    __shared__ float rm[AQ], rl[AQ], rc[AQ];

    const int b  = blockIdx.z;
    const int h  = blockIdx.y;
    const int q0 = blockIdx.x * AQ;
    const int tid = threadIdx.x;
    const int tx = tid & 7;
    const int ty = tid >> 3;

    const float* qb = Qp + ((long)b * Sq) * Dd + h * DHd;
    const float* kb = Kp + (long)b * kvbs + h * DHd;
    const float* vb = Vp + (long)b * kvbs + h * DHd;

    for (int i = tid; i < AQ * DHd; i += 128)
        Qs[i >> 6][i & 63] = qb[(long)(q0 + (i >> 6)) * Dd + (i & 63)];
    if (tid < AQ) { rm[tid] = -1e30f; rl[tid] = 0.f; }

    float Oacc[4][8];
    #pragma unroll
    for (int i = 0; i < 4; i++)
        #pragma unroll
        for (int j = 0; j < 8; j++) Oacc[i][j] = 0.f;

    const int ntiles = Sk / AK;
    for (int kt = 0; kt < ntiles; kt++) {
        const int k0 = kt * AK;
        __syncthreads();
        for (int i = tid; i < AK * DHd; i += 128) {
            int r = i >> 6, c = i & 63;
            Ks[r][c] = kb[(long)(k0 + r) * Dd + c];
            Vs[r][c] = vb[(long)(k0 + r) * Dd + c];
        }
        __syncthreads();

        float sacc[4][4];
        #pragma unroll
        for (int i = 0; i < 4; i++)
            #pragma unroll
            for (int j = 0; j < 4; j++) sacc[i][j] = 0.f;
        #pragma unroll 8
        for (int d = 0; d < DHd; d++) {
            float qr[4], kr[4];
            #pragma unroll
            for (int i = 0; i < 4; i++) qr[i] = Qs[ty*4 + i][d];
            #pragma unroll
            for (int j = 0; j < 4; j++) kr[j] = Ks[tx*4 + j][d];
            #pragma unroll
            for (int i = 0; i < 4; i++)
                #pragma unroll
                for (int j = 0; j < 4; j++) sacc[i][j] += qr[i] * kr[j];
        }
        #pragma unroll
        for (int i = 0; i < 4; i++) {
            #pragma unroll
            for (int j = 0; j < 4; j++) {
                float sc = sacc[i][j] * 0.125f;
                if (band) {
                    int qi = q0 + ty*4 + i, ki = k0 + tx*4 + j;
                    int dlt = qi - ki; if (dlt < 0) dlt = -dlt;
                    sc += (dlt <= Rr) ? 1.0f : 0.0f;
                }
                Ps[ty*4 + i][tx*4 + j] = sc;
            }
        }
        __syncthreads();

        if (tid < AQ) {
            float mo = rm[tid], mx = mo;
            #pragma unroll 8
            for (int j = 0; j < AK; j++) mx = fmaxf(mx, Ps[tid][j]);
            float cc = __expf(mo - mx);
            float sum = 0.f;
            #pragma unroll 8
            for (int j = 0; j < AK; j++) {
                float p = __expf(Ps[tid][j] - mx);
                Ps[tid][j] = p; sum += p;
            }
            rl[tid] = rl[tid] * cc + sum;
            rm[tid] = mx; rc[tid] = cc;
        }
        __syncthreads();

        #pragma unroll
        for (int i = 0; i < 4; i++) {
            float ci = rc[ty*4 + i];
            #pragma unroll
            for (int j = 0; j < 8; j++) Oacc[i][j] *= ci;
        }
        #pragma unroll 4
        for (int kk = 0; kk < AK; kk++) {
            float p[4], vv[8];
            #pragma unroll
            for (int i = 0; i < 4; i++) p[i] = Ps[ty*4 + i][kk];
            #pragma unroll
            for (int j = 0; j < 8; j++) vv[j] = Vs[kk][tx*8 + j];
            #pragma unroll
            for (int i = 0; i < 4; i++)
                #pragma unroll
                for (int j = 0; j < 8; j++) Oacc[i][j] += p[i] * vv[j];
        }
    }

    const long obase = ((long)b * Sq + q0) * Dd + h * DHd;
    #pragma unroll
    for (int i = 0; i < 4; i++) {
        int r = ty*4 + i;
        float inv = 1.0f / rl[r];
        #pragma unroll
        for (int j2 = 0; j2 < 4; j2++) {
            float v0 = Oacc[i][j2*2    ] * inv;
            float v1 = Oacc[i][j2*2 + 1] * inv;
            __nv_bfloat16 h0,h1,l0,l1;
            split_bf(v0,h0,l0); split_bf(v1,h1,l1);
            long off = obase + (long)r * Dd + tx*8 + j2*2;
            *(uint32_t*)(Ohp + off) = pack_bf2(h0,h1);
            *(uint32_t*)(Olp + off) = pack_bf2(l0,l1);
        }
    }
}

// ---------------- LayerNorm (row per block, optional bf16 hi/lo out) --------
__global__ __launch_bounds__(256)
void ln_kernel(const float* __restrict__ in, const float* __restrict__ g,
               const float* __restrict__ bta, float* __restrict__ out,
               __nv_bfloat16* __restrict__ oh, __nv_bfloat16* __restrict__ ol)
{
    const int row = blockIdx.x;
    const float* x = in + (long)row * Dd;
    const int tid = threadIdx.x;

    float v0 = x[tid], v1 = x[tid + 256], v2 = x[tid + 512];
    float s = v0 + v1 + v2;

    __shared__ float sred[8];
    __shared__ float smean, svar;

    #pragma unroll
    for (int off = 16; off; off >>= 1) s += __shfl_xor_sync(0xffffffffu, s, off);
    if ((tid & 31) == 0) sred[tid >> 5] = s;
    __syncthreads();
    if (tid == 0) {
        float t = 0.f;
        #pragma unroll
        for (int i = 0; i < 8; i++) t += sred[i];
        smean = t * (1.0f / Dd);
    }
    __syncthreads();
    float m = smean;
    float d0 = v0 - m, d1 = v1 - m, d2 = v2 - m;
    float sq = d0*d0 + d1*d1 + d2*d2;
    #pragma unroll
    for (int off = 16; off; off >>= 1) sq += __shfl_xor_sync(0xffffffffu, sq, off);
    if ((tid & 31) == 0) sred[tid >> 5] = sq;
    __syncthreads();
    if (tid == 0) {
        float t = 0.f;
        #pragma unroll
        for (int i = 0; i < 8; i++) t += sred[i];
        svar = t * (1.0f / Dd);
    }
    __syncthreads();
    float inv = rsqrtf(svar + 1e-12f);
    #pragma unroll
    for (int u = 0; u < 3; u++) {
        int idx = tid + u * 256;
        float d = (u == 0 ? d0 : (u == 1 ? d1 : d2));
        float val = d * inv * g[idx] + bta[idx];
        out[(long)row * Dd + idx] = val;
        if (oh) {
            __nv_bfloat16 h, l; split_bf(val, h, l);
            oh[(long)row * Dd + idx] = h;
            ol[(long)row * Dd + idx] = l;
        }
    }
}

// ---------------- launch ----------------------------------------------------
typedef void (*gemm_fn)(const __nv_bfloat16*, const __nv_bfloat16*,
                        const __nv_bfloat16*, const __nv_bfloat16*,
                        const float*, const float*,
                        float*, __nv_bfloat16*, __nv_bfloat16*, int, int, int);

static inline void launch_gemm_t(gemm_fn fn,
                                 const __nv_bfloat16* Ah, const __nv_bfloat16* Al,
                                 const __nv_bfloat16* Bh, const __nv_bfloat16* Bl,
                                 const float* bias, const float* Rz,
                                 float* C, __nv_bfloat16* Ch, __nv_bfloat16* Cl,
                                 int M, int N, int K)
{
    dim3 g(N / 128, (M + 127) / 128);
    cudaFuncSetAttribute((const void*)fn, cudaFuncAttributeMaxDynamicSharedMemorySize, 2 * STG_B);
    fn<<<g, 256, 2 * STG_B>>>(Ah, Al, Bh, Bl, bias, Rz, C, Ch, Cl, M, N, K);
}

extern "C" void kernel_launch(void* const* d_in, const int* in_sizes, int n_in,
                              void* d_out, int out_size)
{
    const float* X     = (const float*)d_in[0];
    const float* tag   = (const float*)d_in[1];
    const float* sa_wq = (const float*)d_in[2];  const float* sa_bq = (const float*)d_in[3];
    const float* sa_wk = (const float*)d_in[4];  const float* sa_bk = (const float*)d_in[5];
    const float* sa_wv = (const float*)d_in[6];  const float* sa_bv = (const float*)d_in[7];
    const float* sa_wo = (const float*)d_in[8];  const float* sa_bo = (const float*)d_in[9];
    const float* sa_lg = (const float*)d_in[10]; const float* sa_lb = (const float*)d_in[11];
    const float* ca_wq = (const float*)d_in[12]; const float* ca_bq = (const float*)d_in[13];
    const float* ca_wk = (const float*)d_in[14]; const float* ca_bk = (const float*)d_in[15];
    const float* ca_wv = (const float*)d_in[16]; const float* ca_bv = (const float*)d_in[17];
    const float* ca_wo = (const float*)d_in[18]; const float* ca_bo = (const float*)d_in[19];
    const float* ca_lg = (const float*)d_in[20]; const float* ca_lb = (const float*)d_in[21];
    const float* ff_w1 = (const float*)d_in[22]; const float* ff_b1 = (const float*)d_in[23];
    const float* ff_w2 = (const float*)d_in[24]; const float* ff_b2 = (const float*)d_in[25];
    const float* ff_lg = (const float*)d_in[26]; const float* ff_lb = (const float*)d_in[27];
    float* out = (float*)d_out;

    float *q, *k, *v, *t1, *x1, *x2, *ck, *cv;
    cudaGetSymbolAddress((void**)&q,  g_q);  cudaGetSymbolAddress((void**)&k,  g_k);
    cudaGetSymbolAddress((void**)&v,  g_v);  cudaGetSymbolAddress((void**)&t1, g_t1);
    cudaGetSymbolAddress((void**)&x1, g_x1); cudaGetSymbolAddress((void**)&x2, g_x2);
    cudaGetSymbolAddress((void**)&ck, g_ck); cudaGetSymbolAddress((void**)&cv, g_cv);

    __nv_bfloat16 *xh,*xl,*x1h,*x1l,*x2h,*x2l,*cth,*ctl,*ffh,*ffl,*tgh,*tgl,*wh,*wl;
    cudaGetSymbolAddress((void**)&xh,  g_xh);  cudaGetSymbolAddress((void**)&xl,  g_xl);
    cudaGetSymbolAddress((void**)&x1h, g_x1h); cudaGetSymbolAddress((void**)&x1l, g_x1l);
    cudaGetSymbolAddress((void**)&x2h, g_x2h); cudaGetSymbolAddress((void**)&x2l, g_x2l);
    cudaGetSymbolAddress((void**)&cth, g_cth); cudaGetSymbolAddress((void**)&ctl, g_ctl);
    cudaGetSymbolAddress((void**)&ffh, g_ffh); cudaGetSymbolAddress((void**)&ffl, g_ffl);
    cudaGetSymbolAddress((void**)&tgh, g_tgh); cudaGetSymbolAddress((void**)&tgl, g_tgl);
    cudaGetSymbolAddress((void**)&wh,  g_wh);  cudaGetSymbolAddress((void**)&wl,  g_wl);

    const int M = MTOT;
    dim3 agrid(Ss / AQ, Hh, Bb);
    dim3 tb(32, 8);

    // ---- pre-convert activations & weights ----
    fconv<<<(M*Dd/4 + 255)/256, 256>>>(X, xh, xl, M*Dd/4);
    fconv<<<(Tt*Dd/4 + 255)/256, 256>>>(tag, tgh, tgl, Tt*Dd/4);

    const float* ws[10]  = {sa_wq, sa_wk, sa_wv, sa_wo, ca_wq, ca_wk, ca_wv, ca_wo, ff_w1, ff_w2};
    const long  woff[10] = {0, WSZ, 2*WSZ, 3*WSZ, 4*WSZ, 5*WSZ, 6*WSZ, 7*WSZ, WOFF_FF1, WOFF_FF2};
    const int   wk_[10]  = {Dd,Dd,Dd,Dd,Dd,Dd,Dd,Dd,Dd,FFd};
    const int   wn_[10]  = {Dd,Dd,Dd,Dd,Dd,Dd,Dd,Dd,FFd,Dd};
    for (int i = 0; i < 10; i++) {
        dim3 wg(wn_[i]/32, wk_[i]/32);
        wtconv<<<wg, tb>>>(ws[i], wh + woff[i], wl + woff[i], wk_[i], wn_[i]);
    }

    // ---- self-attention ----
    launch_gemm_t(gemm_bf<0,0,1,0>, xh, xl, wh+0*WSZ, wl+0*WSZ, sa_bq, nullptr, q, nullptr, nullptr, M, Dd, Dd);
    launch_gemm_t(gemm_bf<0,0,1,0>, xh, xl, wh+1*WSZ, wl+1*WSZ, sa_bk, nullptr, k, nullptr, nullptr, M, Dd, Dd);
    launch_gemm_t(gemm_bf<0,0,1,0>, xh, xl, wh+2*WSZ, wl+2*WSZ, sa_bv, nullptr, v, nullptr, nullptr, M, Dd, Dd);
    attn_kernel<<<agrid, 128>>>(q, k, v, cth, ctl, Ss, Ss, (long)Ss * Dd, 1);
    launch_gemm_t(gemm_bf<0,1,1,0>, cth, ctl, wh+3*WSZ, wl+3*WSZ, sa_bo, X, t1, nullptr, nullptr, M, Dd, Dd);
    ln_kernel<<<M, 256>>>(t1, sa_lg, sa_lb, x1, x1h, x1l);

    // ---- cross-attention (keys/values from 64 tag embeddings) ----
    launch_gemm_t(gemm_bf<0,0,1,0>, x1h, x1l, wh+4*WSZ, wl+4*WSZ, ca_bq, nullptr, q, nullptr, nullptr, M, Dd, Dd);
    launch_gemm_t(gemm_bf<0,0,1,0>, tgh, tgl, wh+5*WSZ, wl+5*WSZ, ca_bk, nullptr, ck, nullptr, nullptr, Tt, Dd, Dd);
    launch_gemm_t(gemm_bf<0,0,1,0>, tgh, tgl, wh+6*WSZ, wl+6*WSZ, ca_bv, nullptr, cv, nullptr, nullptr, Tt, Dd, Dd);
    attn_kernel<<<agrid, 128>>>(q, ck, cv, cth, ctl, Ss, Tt, 0L, 0);
    launch_gemm_t(gemm_bf<0,1,1,0>, cth, ctl, wh+7*WSZ, wl+7*WSZ, ca_bo, x1, t1, nullptr, nullptr, M, Dd, Dd);
    ln_kernel<<<M, 256>>>(t1, ca_lg, ca_lb, x2, x2h, x2l);

    // ---- FFN ----
    launch_gemm_t(gemm_bf<1,0,0,1>, x2h, x2l, wh+WOFF_FF1, wl+WOFF_FF1, ff_b1, nullptr, nullptr, ffh, ffl, M, FFd, Dd);
    launch_gemm_t(gemm_bf<0,1,1,0>, ffh, ffl, wh+WOFF_FF2, wl+WOFF_FF2, ff_b2, x2, t1, nullptr, nullptr, M, Dd, FFd);
    ln_kernel<<<M, 256>>>(t1, ff_lg, ff_lb, out, nullptr, nullptr);
}

// round 8
// speedup vs baseline: 2.4395x; 1.4522x over previous
#include <cuda_runtime.h>
#include <cuda_bf16.h>
#include <math.h>
#include <cstdint>

// Problem constants
#define Bb   2
#define Ss   2048
#define Dd   768
#define Hh   12
#define DHd  64
#define Tt   64
#define FFd  3072
#define Rr   50

#define MTOT (Bb*Ss)        // 4096

// ---------------- scratch (device globals; no allocations allowed) ----------
__device__ float g_t1 [MTOT*Dd];
__device__ float g_x1 [MTOT*Dd];
__device__ float g_x2 [MTOT*Dd];

// bf16 hi/lo buffers
__device__ __nv_bfloat16 g_xh [MTOT*Dd],  g_xl [MTOT*Dd];
__device__ __nv_bfloat16 g_x1h[MTOT*Dd],  g_x1l[MTOT*Dd];
__device__ __nv_bfloat16 g_x2h[MTOT*Dd],  g_x2l[MTOT*Dd];
__device__ __nv_bfloat16 g_cth[MTOT*Dd],  g_ctl[MTOT*Dd];
__device__ __nv_bfloat16 g_ffh[MTOT*FFd], g_ffl[MTOT*FFd];
__device__ __nv_bfloat16 g_tgh[Tt*Dd],    g_tgl[Tt*Dd];
__device__ __nv_bfloat16 g_qh [MTOT*Dd],  g_ql [MTOT*Dd];
__device__ __nv_bfloat16 g_kh [MTOT*Dd],  g_kl [MTOT*Dd];
__device__ __nv_bfloat16 g_vth[Dd*MTOT],  g_vtl[Dd*MTOT];   // V^T [n][m]
__device__ __nv_bfloat16 g_ckh[Tt*Dd],    g_ckl[Tt*Dd];
__device__ __nv_bfloat16 g_cvth[Dd*Tt],   g_cvtl[Dd*Tt];    // cross V^T

// transposed weights [N][K] hi/lo
#define WSZ  (Dd*Dd)
#define WOFF_FF1 (8*WSZ)
#define WOFF_FF2 (WOFF_FF1 + Dd*FFd)
#define WTOT (WOFF_FF2 + FFd*Dd)
__device__ __nv_bfloat16 g_wh[WTOT], g_wl[WTOT];

// =============== helpers =====================================================
__device__ __forceinline__ void mma16816(float* c, const uint32_t* a, const uint32_t* b) {
    asm volatile(
        "mma.sync.aligned.m16n8k16.row.col.f32.bf16.bf16.f32 "
        "{%0,%1,%2,%3}, {%4,%5,%6,%7}, {%8,%9}, {%0,%1,%2,%3};\n"
        : "+f"(c[0]), "+f"(c[1]), "+f"(c[2]), "+f"(c[3])
        : "r"(a[0]), "r"(a[1]), "r"(a[2]), "r"(a[3]), "r"(b[0]), "r"(b[1]));
}
__device__ __forceinline__ uint32_t pack_bf2(__nv_bfloat16 a, __nv_bfloat16 b) {
    return ((uint32_t)__bfloat16_as_ushort(b) << 16) | (uint32_t)__bfloat16_as_ushort(a);
}
__device__ __forceinline__ uint32_t smem_u32(const void* p) {
    uint32_t a;
    asm("{ .reg .u64 t; cvta.to.shared.u64 t, %1; cvt.u32.u64 %0, t; }" : "=r"(a) : "l"(p));
    return a;
}
__device__ __forceinline__ void cpa16(uint32_t dst, const void* src, bool valid) {
    int sz = valid ? 16 : 0;
    asm volatile("cp.async.cg.shared.global [%0], [%1], 16, %2;"
                 :: "r"(dst), "l"(src), "r"(sz));
}
#define CP_COMMIT() asm volatile("cp.async.commit_group;" ::: "memory")
#define CP_WAIT(n)  asm volatile("cp.async.wait_group %0;" :: "n"(n) : "memory")

__device__ __forceinline__ void split_bf(float v, __nv_bfloat16& h, __nv_bfloat16& l) {
    h = __float2bfloat16(v);
    l = __float2bfloat16(v - __bfloat162float(h));
}

// ============ conversion kernels ============================================
__global__ void fconv(const float* __restrict__ x, __nv_bfloat16* __restrict__ h,
                      __nv_bfloat16* __restrict__ l, int n4)
{
    int i = blockIdx.x * 256 + threadIdx.x;
    if (i >= n4) return;
    float4 v = ((const float4*)x)[i];
    __nv_bfloat16 h0,h1,h2,h3,l0,l1,l2,l3;
    split_bf(v.x,h0,l0); split_bf(v.y,h1,l1); split_bf(v.z,h2,l2); split_bf(v.w,h3,l3);
    ((uint2*)h)[i] = make_uint2(pack_bf2(h0,h1), pack_bf2(h2,h3));
    ((uint2*)l)[i] = make_uint2(pack_bf2(l0,l1), pack_bf2(l2,l3));
}

__global__ void wtconv(const float* __restrict__ W, __nv_bfloat16* __restrict__ Wh,
                       __nv_bfloat16* __restrict__ Wl, int K, int N)
{
    __shared__ float t[32][33];
    const int k0 = blockIdx.y * 32, n0 = blockIdx.x * 32;
    const int tx = threadIdx.x, ty = threadIdx.y;   // 32 x 8
    #pragma unroll
    for (int i = 0; i < 4; i++)
        t[ty + i*8][tx] = W[(long)(k0 + ty + i*8) * N + n0 + tx];
    __syncthreads();
    #pragma unroll
    for (int i = 0; i < 4; i++) {
        int n = n0 + ty + i*8;
        float v = t[tx][ty + i*8];
        __nv_bfloat16 h, l; split_bf(v, h, l);
        Wh[(long)n * K + k0 + tx] = h;
        Wl[(long)n * K + k0 + tx] = l;
    }
}

// ======== split-bf16 tensor-core GEMM ========================================
// OMODE: 0 = fp32 C, 1 = bf16 hi/lo, 2 = bf16 hi/lo TRANSPOSED [n][m] (ldt)
#define STG_B 40960

template<int ACT, int RES, int OMODE>
__global__ void __launch_bounds__(256)
gemm_bf(const __nv_bfloat16* __restrict__ Ahp, const __nv_bfloat16* __restrict__ Alp,
        const __nv_bfloat16* __restrict__ Bhp, const __nv_bfloat16* __restrict__ Blp,
        const float* __restrict__ bias, const float* __restrict__ Rz,
        float* __restrict__ C, __nv_bfloat16* __restrict__ Chp, __nv_bfloat16* __restrict__ Clp,
        int M, int N, int K, int ldt)
{
    extern __shared__ char smem[];
    const uint32_t sb = smem_u32(smem);
    const int tid  = threadIdx.x;
    const int wid  = tid >> 5;
    const int lane = tid & 31;
    const int wm   = (wid & 1) * 64;
    const int wn   = (wid >> 1) * 32;
    const int bm   = blockIdx.y * 128;
    const int bn   = blockIdx.x * 128;
    const int nch  = K >> 5;
    const int gq = lane >> 2;
    const int gt = lane & 3;

    float acc[4][4][4];
    #pragma unroll
    for (int i = 0; i < 4; i++)
        #pragma unroll
        for (int j = 0; j < 4; j++)
            #pragma unroll
            for (int e = 0; e < 4; e++) acc[i][j][e] = 0.f;

    const __nv_bfloat16* srcs[4] = {Ahp, Alp, Bhp, Blp};

    auto load_stage = [&](int s, int k0) {
        #pragma unroll
        for (int a = 0; a < 4; a++) {
            #pragma unroll
            for (int t = 0; t < 2; t++) {
                int q   = tid + t * 256;
                int row = q >> 2, c4 = q & 3;
                int grow = (a < 2) ? (bm + row) : (bn + row);
                bool valid = (a < 2) ? (grow < M) : true;
                const __nv_bfloat16* src = srcs[a] + (long)(valid ? grow : 0) * K + k0 + c4 * 8;
                cpa16(sb + s * STG_B + a * 10240 + row * 80 + c4 * 16, src, valid);
            }
        }
    };

    load_stage(0, 0);
    CP_COMMIT();

    for (int c = 0; c < nch; c++) {
        if (c + 1 < nch) { load_stage((c + 1) & 1, (c + 1) * 32); CP_COMMIT(); CP_WAIT(1); }
        else             { CP_WAIT(0); }
        __syncthreads();

        const char* st = smem + (c & 1) * STG_B;
        const char* sAh = st;
        const char* sAl = st + 10240;
        const char* sBh = st + 20480;
        const char* sBl = st + 30720;

        #pragma unroll
        for (int ks = 0; ks < 2; ks++) {
            const int kk = ks * 16 + gt * 2;
            uint32_t bhf[4][2], blf[4][2];
            #pragma unroll
            for (int j = 0; j < 4; j++) {
                int nr = wn + j * 8 + gq;
                bhf[j][0] = *(const uint32_t*)(sBh + nr * 80 + kk * 2);
                bhf[j][1] = *(const uint32_t*)(sBh + nr * 80 + (kk + 8) * 2);
                blf[j][0] = *(const uint32_t*)(sBl + nr * 80 + kk * 2);
                blf[j][1] = *(const uint32_t*)(sBl + nr * 80 + (kk + 8) * 2);
            }
            #pragma unroll
            for (int i = 0; i < 4; i++) {
                int r0 = wm + i * 16 + gq;
                uint32_t ahf[4], alf[4];
                ahf[0] = *(const uint32_t*)(sAh + r0 * 80 + kk * 2);
                ahf[1] = *(const uint32_t*)(sAh + (r0 + 8) * 80 + kk * 2);
                ahf[2] = *(const uint32_t*)(sAh + r0 * 80 + (kk + 8) * 2);
                ahf[3] = *(const uint32_t*)(sAh + (r0 + 8) * 80 + (kk + 8) * 2);
                alf[0] = *(const uint32_t*)(sAl + r0 * 80 + kk * 2);
                alf[1] = *(const uint32_t*)(sAl + (r0 + 8) * 80 + kk * 2);
                alf[2] = *(const uint32_t*)(sAl + r0 * 80 + (kk + 8) * 2);
                alf[3] = *(const uint32_t*)(sAl + (r0 + 8) * 80 + (kk + 8) * 2);
                #pragma unroll
                for (int j = 0; j < 4; j++) {
                    mma16816(acc[i][j], ahf, bhf[j]);
                    mma16816(acc[i][j], alf, bhf[j]);
                    mma16816(acc[i][j], ahf, blf[j]);
                }
            }
        }
        __syncthreads();
    }

    #pragma unroll
    for (int i = 0; i < 4; i++) {
        #pragma unroll
        for (int rr = 0; rr < 2; rr++) {
            int m = bm + wm + i * 16 + gq + rr * 8;
            if (m >= M) continue;
            #pragma unroll
            for (int j = 0; j < 4; j++) {
                int n = bn + wn + j * 8 + gt * 2;
                float v0 = acc[i][j][rr * 2 + 0] + __ldg(&bias[n]);
                float v1 = acc[i][j][rr * 2 + 1] + __ldg(&bias[n + 1]);
                if (RES) {
                    const float* rp = Rz + (long)m * N + n;
                    v0 += rp[0]; v1 += rp[1];
                }
                if (ACT) {
                    v0 = 0.5f * v0 * (1.0f + erff(v0 * 0.70710678118654752f));
                    v1 = 0.5f * v1 * (1.0f + erff(v1 * 0.70710678118654752f));
                }
                if (OMODE == 0)
                    *(float2*)(C + (long)m * N + n) = make_float2(v0, v1);
                if (OMODE == 1) {
                    __nv_bfloat16 h0,h1,l0,l1;
                    split_bf(v0,h0,l0); split_bf(v1,h1,l1);
                    *(uint32_t*)(Chp + (long)m * N + n) = pack_bf2(h0,h1);
                    *(uint32_t*)(Clp + (long)m * N + n) = pack_bf2(l0,l1);
                }
                if (OMODE == 2) {
                    __nv_bfloat16 h0,h1,l0,l1;
                    split_bf(v0,h0,l0); split_bf(v1,h1,l1);
                    Chp[(long)n * ldt + m]       = h0;
                    Chp[(long)(n + 1) * ldt + m] = h1;
                    Clp[(long)n * ldt + m]       = l0;
                    Clp[(long)(n + 1) * ldt + m] = l1;
                }
            }
        }
    }
}

// ============ tensor-core flash attention (split bf16) =======================
// CTA: 64 q-rows, 4 warps (16 rows each). K-tile 64 keys, double-buffered.
// Q,K hi/lo as [m][Dd]; V^T hi/lo as [n][m]. Output bf16 hi/lo ctx.
#define ATS   144                 // smem row stride (bytes) for 64 bf16 rows
#define AROWB 9216                // 64 * 144
#define ASTG0 (2*AROWB)           // after Qh, Ql
#define ASTGSZ (4*AROWB)          // Kh,Kl,Vh,Vl
#define ASMEM (ASTG0 + 2*ASTGSZ)  // 92160

__global__ void __launch_bounds__(128)
attn_mma(const __nv_bfloat16* __restrict__ Qh, const __nv_bfloat16* __restrict__ Ql,
         const __nv_bfloat16* __restrict__ Kh, const __nv_bfloat16* __restrict__ Kl,
         const __nv_bfloat16* __restrict__ Vth, const __nv_bfloat16* __restrict__ Vtl,
         __nv_bfloat16* __restrict__ Oh, __nv_bfloat16* __restrict__ Ol,
         int Sk, int kvRowPB, int vtColPB, int ldv, int band)
{
    extern __shared__ char sm[];
    const uint32_t sb = smem_u32(sm);
    const int tid = threadIdx.x;
    const int wq  = tid >> 5;
    const int lane = tid & 31;
    const int gq = lane >> 2, gt = lane & 3;
    const int b = blockIdx.z, h = blockIdx.y, q0 = blockIdx.x * 64;

    // Q tile (loaded once)
    {
        const __nv_bfloat16* qsrc[2] = {Qh, Ql};
        #pragma unroll
        for (int a = 0; a < 2; a++) {
            const __nv_bfloat16* src = qsrc[a] + ((long)(b * Ss + q0)) * Dd + h * DHd;
            #pragma unroll
            for (int it = 0; it < 4; it++) {
                int idx = it * 128 + tid, row = idx >> 3, c4 = idx & 7;
                cpa16(sb + a * AROWB + row * ATS + c4 * 16, src + (long)row * Dd + c4 * 8, true);
            }
        }
    }
    auto loadKV = [&](int stg, int k0) {
        uint32_t so = sb + ASTG0 + (stg & 1) * ASTGSZ;
        const __nv_bfloat16* ks[2] = {Kh, Kl};
        #pragma unroll
        for (int a = 0; a < 2; a++) {
            const __nv_bfloat16* src = ks[a] + ((long)(kvRowPB * b + k0)) * Dd + h * DHd;
            #pragma unroll
            for (int it = 0; it < 4; it++) {
                int idx = it * 128 + tid, row = idx >> 3, c4 = idx & 7;
                cpa16(so + a * AROWB + row * ATS + c4 * 16, src + (long)row * Dd + c4 * 8, true);
            }
        }
        const __nv_bfloat16* vs[2] = {Vth, Vtl};
        #pragma unroll
        for (int a = 0; a < 2; a++) {
            const __nv_bfloat16* src = vs[a] + (long)(h * DHd) * ldv + (long)vtColPB * b + k0;
            #pragma unroll
            for (int it = 0; it < 4; it++) {
                int idx = it * 128 + tid, row = idx >> 3, c4 = idx & 7;
                cpa16(so + (2 + a) * AROWB + row * ATS + c4 * 16, src + (long)row * ldv + c4 * 8, true);
            }
        }
    };
    loadKV(0, 0);
    CP_COMMIT();

    float m0 = -1e30f, m1 = -1e30f, l0 = 0.f, l1 = 0.f;
    float o[8][4];
    #pragma unroll
    for (int j = 0; j < 8; j++)
        #pragma unroll
        for (int e = 0; e < 4; e++) o[j][e] = 0.f;
    uint32_t qfh[4][4], qfl[4][4];

    const int nkt = Sk >> 6;
    for (int t = 0; t < nkt; t++) {
        if (t + 1 < nkt) { loadKV(t + 1, (t + 1) * 64); CP_COMMIT(); CP_WAIT(1); }
        else             { CP_WAIT(0); }
        __syncthreads();

        if (t == 0) {
            const char* sQh = sm;
            const char* sQl = sm + AROWB;
            int r0 = (wq * 16 + gq) * ATS;
            #pragma unroll
            for (int s = 0; s < 4; s++) {
                int kb = (s * 16 + gt * 2) * 2;
                qfh[s][0] = *(const uint32_t*)(sQh + r0 + kb);
                qfh[s][1] = *(const uint32_t*)(sQh + r0 + 8 * ATS + kb);
                qfh[s][2] = *(const uint32_t*)(sQh + r0 + kb + 16);
                qfh[s][3] = *(const uint32_t*)(sQh + r0 + 8 * ATS + kb + 16);
                qfl[s][0] = *(const uint32_t*)(sQl + r0 + kb);
                qfl[s][1] = *(const uint32_t*)(sQl + r0 + 8 * ATS + kb);
                qfl[s][2] = *(const uint32_t*)(sQl + r0 + kb + 16);
                qfl[s][3] = *(const uint32_t*)(sQl + r0 + 8 * ATS + kb + 16);
            }
        }

        const char* st  = sm + ASTG0 + (t & 1) * ASTGSZ;
        const char* sKh = st;
        const char* sKl = st + AROWB;
        const char* sVh = st + 2 * AROWB;
        const char* sVl = st + 3 * AROWB;

        // ---- scores S = Q K^T (split bf16, fp32 accum) ----
        float sc[8][4];
        #pragma unroll
        for (int j = 0; j < 8; j++)
            #pragma unroll
            for (int e = 0; e < 4; e++) sc[j][e] = 0.f;

        #pragma unroll
        for (int j = 0; j < 8; j++) {
            int rb = (j * 8 + gq) * ATS + gt * 4;
            #pragma unroll
            for (int s = 0; s < 4; s++) {
                int off = rb + s * 32;
                uint32_t bh[2] = {*(const uint32_t*)(sKh + off), *(const uint32_t*)(sKh + off + 16)};
                uint32_t bl[2] = {*(const uint32_t*)(sKl + off), *(const uint32_t*)(sKl + off + 16)};
                mma16816(sc[j], qfh[s], bh);
                mma16816(sc[j], qfl[s], bh);
                mma16816(sc[j], qfh[s], bl);
            }
        }

        const int k0 = t * 64;
        const int qi0 = q0 + wq * 16 + gq, qi1 = qi0 + 8;
        #pragma unroll
        for (int j = 0; j < 8; j++) {
            int ki0 = k0 + j * 8 + gt * 2, ki1 = ki0 + 1;
            if (band) {
                int d00 = qi0 - ki0; d00 = d00 < 0 ? -d00 : d00;
                int d01 = qi0 - ki1; d01 = d01 < 0 ? -d01 : d01;
                int d10 = qi1 - ki0; d10 = d10 < 0 ? -d10 : d10;
                int d11 = qi1 - ki1; d11 = d11 < 0 ? -d11 : d11;
                sc[j][0] = sc[j][0] * 0.125f + (d00 <= Rr ? 1.f : 0.f);
                sc[j][1] = sc[j][1] * 0.125f + (d01 <= Rr ? 1.f : 0.f);
                sc[j][2] = sc[j][2] * 0.125f + (d10 <= Rr ? 1.f : 0.f);
                sc[j][3] = sc[j][3] * 0.125f + (d11 <= Rr ? 1.f : 0.f);
            } else {
                sc[j][0] *= 0.125f; sc[j][1] *= 0.125f;
                sc[j][2] *= 0.125f; sc[j][3] *= 0.125f;
            }
        }

        // ---- online softmax (registers + quad shfl) ----
        float nm0 = -1e30f, nm1 = -1e30f;
        #pragma unroll
        for (int j = 0; j < 8; j++) {
            nm0 = fmaxf(nm0, fmaxf(sc[j][0], sc[j][1]));
            nm1 = fmaxf(nm1, fmaxf(sc[j][2], sc[j][3]));
        }
        nm0 = fmaxf(nm0, __shfl_xor_sync(0xffffffffu, nm0, 1));
        nm0 = fmaxf(nm0, __shfl_xor_sync(0xffffffffu, nm0, 2));
        nm1 = fmaxf(nm1, __shfl_xor_sync(0xffffffffu, nm1, 1));
        nm1 = fmaxf(nm1, __shfl_xor_sync(0xffffffffu, nm1, 2));
        float M0 = fmaxf(m0, nm0), M1 = fmaxf(m1, nm1);
        float f0 = __expf(m0 - M0), f1 = __expf(m1 - M1);
        m0 = M0; m1 = M1;

        float s0 = 0.f, s1 = 0.f;
        #pragma unroll
        for (int j = 0; j < 8; j++) {
            sc[j][0] = __expf(sc[j][0] - M0);
            sc[j][1] = __expf(sc[j][1] - M0);
            sc[j][2] = __expf(sc[j][2] - M1);
            sc[j][3] = __expf(sc[j][3] - M1);
            s0 += sc[j][0] + sc[j][1];
            s1 += sc[j][2] + sc[j][3];
        }
        s0 += __shfl_xor_sync(0xffffffffu, s0, 1);
        s0 += __shfl_xor_sync(0xffffffffu, s0, 2);
        s1 += __shfl_xor_sync(0xffffffffu, s1, 1);
        s1 += __shfl_xor_sync(0xffffffffu, s1, 2);
        l0 = l0 * f0 + s0;
        l1 = l1 * f1 + s1;

        #pragma unroll
        for (int j = 0; j < 8; j++) {
            o[j][0] *= f0; o[j][1] *= f0;
            o[j][2] *= f1; o[j][3] *= f1;
        }

        // ---- P fragments (bf16 hi/lo) straight from score accum layout ----
        uint32_t ph[4][4], pl[4][4];
        #pragma unroll
        for (int s = 0; s < 4; s++) {
            __nv_bfloat16 h0,h1,lo0,lo1;
            split_bf(sc[2*s][0], h0, lo0); split_bf(sc[2*s][1], h1, lo1);
            ph[s][0] = pack_bf2(h0,h1); pl[s][0] = pack_bf2(lo0,lo1);
            split_bf(sc[2*s][2], h0, lo0); split_bf(sc[2*s][3], h1, lo1);
            ph[s][1] = pack_bf2(h0,h1); pl[s][1] = pack_bf2(lo0,lo1);
            split_bf(sc[2*s+1][0], h0, lo0); split_bf(sc[2*s+1][1], h1, lo1);
            ph[s][2] = pack_bf2(h0,h1); pl[s][2] = pack_bf2(lo0,lo1);
            split_bf(sc[2*s+1][2], h0, lo0); split_bf(sc[2*s+1][3], h1, lo1);
            ph[s][3] = pack_bf2(h0,h1); pl[s][3] = pack_bf2(lo0,lo1);
        }

        // ---- O += P V (split bf16) ----
        #pragma unroll
        for (int jd = 0; jd < 8; jd++) {
            int rb = (jd * 8 + gq) * ATS + gt * 4;
            #pragma unroll
            for (int s = 0; s < 4; s++) {
                int off = rb + s * 32;
                uint32_t vh[2] = {*(const uint32_t*)(sVh + off), *(const uint32_t*)(sVh + off + 16)};
                uint32_t vl[2] = {*(const uint32_t*)(sVl + off), *(const uint32_t*)(sVl + off + 16)};
                mma16816(o[jd], ph[s], vh);
                mma16816(o[jd], pl[s], vh);
                mma16816(o[jd], ph[s], vl);
            }
        }
        __syncthreads();
    }

    // ---- write ctx as bf16 hi/lo ----
    float i0 = 1.f / l0, i1 = 1.f / l1;
    long r0g = (long)(b * Ss) + q0 + wq * 16 + gq;
    #pragma unroll
    for (int jd = 0; jd < 8; jd++) {
        int col = h * DHd + jd * 8 + gt * 2;
        float v0 = o[jd][0] * i0, v1 = o[jd][1] * i0;
        float v2 = o[jd][2] * i1, v3 = o[jd][3] * i1;
        __nv_bfloat16 h0,h1,lo0,lo1;
        split_bf(v0,h0,lo0); split_bf(v1,h1,lo1);
        *(uint32_t*)(Oh + r0g * Dd + col) = pack_bf2(h0,h1);
        *(uint32_t*)(Ol + r0g * Dd + col) = pack_bf2(lo0,lo1);
        split_bf(v2,h0,lo0); split_bf(v3,h1,lo1);
        *(uint32_t*)(Oh + (r0g + 8) * Dd + col) = pack_bf2(h0,h1);
        *(uint32_t*)(Ol + (r0g + 8) * Dd + col) = pack_bf2(lo0,lo1);
    }
}

// ---------------- LayerNorm ---------------------------------------------
__global__ __launch_bounds__(256)
void ln_kernel(const float* __restrict__ in, const float* __restrict__ g,
               const float* __restrict__ bta, float* __restrict__ out,
               __nv_bfloat16* __restrict__ oh, __nv_bfloat16* __restrict__ ol)
{
    const int row = blockIdx.x;
    const float* x = in + (long)row * Dd;
    const int tid = threadIdx.x;

    float v0 = x[tid], v1 = x[tid + 256], v2 = x[tid + 512];
    float s = v0 + v1 + v2;

    __shared__ float sred[8];
    __shared__ float smean, svar;

    #pragma unroll
    for (int off = 16; off; off >>= 1) s += __shfl_xor_sync(0xffffffffu, s, off);
    if ((tid & 31) == 0) sred[tid >> 5] = s;
    __syncthreads();
    if (tid == 0) {
        float t = 0.f;
        #pragma unroll
        for (int i = 0; i < 8; i++) t += sred[i];
        smean = t * (1.0f / Dd);
    }
    __syncthreads();
    float m = smean;
    float d0 = v0 - m, d1 = v1 - m, d2 = v2 - m;
    float sq = d0*d0 + d1*d1 + d2*d2;
    #pragma unroll
    for (int off = 16; off; off >>= 1) sq += __shfl_xor_sync(0xffffffffu, sq, off);
    if ((tid & 31) == 0) sred[tid >> 5] = sq;
    __syncthreads();
    if (tid == 0) {
        float t = 0.f;
        #pragma unroll
        for (int i = 0; i < 8; i++) t += sred[i];
        svar = t * (1.0f / Dd);
    }
    __syncthreads();
    float inv = rsqrtf(svar + 1e-12f);
    #pragma unroll
    for (int u = 0; u < 3; u++) {
        int idx = tid + u * 256;
        float d = (u == 0 ? d0 : (u == 1 ? d1 : d2));
        float val = d * inv * g[idx] + bta[idx];
        out[(long)row * Dd + idx] = val;
        if (oh) {
            __nv_bfloat16 hh, ll; split_bf(val, hh, ll);
            oh[(long)row * Dd + idx] = hh;
            ol[(long)row * Dd + idx] = ll;
        }
    }
}

// ---------------- launch ----------------------------------------------------
typedef void (*gemm_fn)(const __nv_bfloat16*, const __nv_bfloat16*,
                        const __nv_bfloat16*, const __nv_bfloat16*,
                        const float*, const float*,
                        float*, __nv_bfloat16*, __nv_bfloat16*, int, int, int, int);

static inline void launch_gemm_t(gemm_fn fn,
                                 const __nv_bfloat16* Ah, const __nv_bfloat16* Al,
                                 const __nv_bfloat16* Bh, const __nv_bfloat16* Bl,
                                 const float* bias, const float* Rz,
                                 float* C, __nv_bfloat16* Ch, __nv_bfloat16* Cl,
                                 int M, int N, int K, int ldt)
{
    dim3 g(N / 128, (M + 127) / 128);
    cudaFuncSetAttribute((const void*)fn, cudaFuncAttributeMaxDynamicSharedMemorySize, 2 * STG_B);
    fn<<<g, 256, 2 * STG_B>>>(Ah, Al, Bh, Bl, bias, Rz, C, Ch, Cl, M, N, K, ldt);
}

extern "C" void kernel_launch(void* const* d_in, const int* in_sizes, int n_in,
                              void* d_out, int out_size)
{
    const float* X     = (const float*)d_in[0];
    const float* tag   = (const float*)d_in[1];
    const float* sa_wq = (const float*)d_in[2];  const float* sa_bq = (const float*)d_in[3];
    const float* sa_wk = (const float*)d_in[4];  const float* sa_bk = (const float*)d_in[5];
    const float* sa_wv = (const float*)d_in[6];  const float* sa_bv = (const float*)d_in[7];
    const float* sa_wo = (const float*)d_in[8];  const float* sa_bo = (const float*)d_in[9];
    const float* sa_lg = (const float*)d_in[10]; const float* sa_lb = (const float*)d_in[11];
    const float* ca_wq = (const float*)d_in[12]; const float* ca_bq = (const float*)d_in[13];
    const float* ca_wk = (const float*)d_in[14]; const float* ca_bk = (const float*)d_in[15];
    const float* ca_wv = (const float*)d_in[16]; const float* ca_bv = (const float*)d_in[17];
    const float* ca_wo = (const float*)d_in[18]; const float* ca_bo = (const float*)d_in[19];
    const float* ca_lg = (const float*)d_in[20]; const float* ca_lb = (const float*)d_in[21];
    const float* ff_w1 = (const float*)d_in[22]; const float* ff_b1 = (const float*)d_in[23];
    const float* ff_w2 = (const float*)d_in[24]; const float* ff_b2 = (const float*)d_in[25];
    const float* ff_lg = (const float*)d_in[26]; const float* ff_lb = (const float*)d_in[27];
    float* out = (float*)d_out;

    float *t1, *x1, *x2;
    cudaGetSymbolAddress((void**)&t1, g_t1);
    cudaGetSymbolAddress((void**)&x1, g_x1); cudaGetSymbolAddress((void**)&x2, g_x2);

    __nv_bfloat16 *xh,*xl,*x1h,*x1l,*x2h,*x2l,*cth,*ctl,*ffh,*ffl,*tgh,*tgl,*wh,*wl;
    __nv_bfloat16 *qh,*ql,*kh,*kl,*vth,*vtl,*ckh,*ckl,*cvth,*cvtl;
    cudaGetSymbolAddress((void**)&xh,  g_xh);  cudaGetSymbolAddress((void**)&xl,  g_xl);
    cudaGetSymbolAddress((void**)&x1h, g_x1h); cudaGetSymbolAddress((void**)&x1l, g_x1l);
    cudaGetSymbolAddress((void**)&x2h, g_x2h); cudaGetSymbolAddress((void**)&x2l, g_x2l);
    cudaGetSymbolAddress((void**)&cth, g_cth); cudaGetSymbolAddress((void**)&ctl, g_ctl);
    cudaGetSymbolAddress((void**)&ffh, g_ffh); cudaGetSymbolAddress((void**)&ffl, g_ffl);
    cudaGetSymbolAddress((void**)&tgh, g_tgh); cudaGetSymbolAddress((void**)&tgl, g_tgl);
    cudaGetSymbolAddress((void**)&wh,  g_wh);  cudaGetSymbolAddress((void**)&wl,  g_wl);
    cudaGetSymbolAddress((void**)&qh,  g_qh);  cudaGetSymbolAddress((void**)&ql,  g_ql);
    cudaGetSymbolAddress((void**)&kh,  g_kh);  cudaGetSymbolAddress((void**)&kl,  g_kl);
    cudaGetSymbolAddress((void**)&vth, g_vth); cudaGetSymbolAddress((void**)&vtl, g_vtl);
    cudaGetSymbolAddress((void**)&ckh, g_ckh); cudaGetSymbolAddress((void**)&ckl, g_ckl);
    cudaGetSymbolAddress((void**)&cvth,g_cvth);cudaGetSymbolAddress((void**)&cvtl,g_cvtl);

    const int M = MTOT;
    dim3 agrid(Ss / 64, Hh, Bb);
    dim3 tb(32, 8);

    cudaFuncSetAttribute(attn_mma, cudaFuncAttributeMaxDynamicSharedMemorySize, ASMEM);

    // ---- pre-convert activations & weights ----
    fconv<<<(M*Dd/4 + 255)/256, 256>>>(X, xh, xl, M*Dd/4);
    fconv<<<(Tt*Dd/4 + 255)/256, 256>>>(tag, tgh, tgl, Tt*Dd/4);

    const float* ws[10]  = {sa_wq, sa_wk, sa_wv, sa_wo, ca_wq, ca_wk, ca_wv, ca_wo, ff_w1, ff_w2};
    const long  woff[10] = {0, WSZ, 2*WSZ, 3*WSZ, 4*WSZ, 5*WSZ, 6*WSZ, 7*WSZ, WOFF_FF1, WOFF_FF2};
    const int   wk_[10]  = {Dd,Dd,Dd,Dd,Dd,Dd,Dd,Dd,Dd,FFd};
    const int   wn_[10]  = {Dd,Dd,Dd,Dd,Dd,Dd,Dd,Dd,FFd,Dd};
    for (int i = 0; i < 10; i++) {
        dim3 wg(wn_[i]/32, wk_[i]/32);
        wtconv<<<wg, tb>>>(ws[i], wh + woff[i], wl + woff[i], wk_[i], wn_[i]);
    }

    // ---- self-attention ----
    launch_gemm_t(gemm_bf<0,0,1>, xh, xl, wh+0*WSZ, wl+0*WSZ, sa_bq, nullptr, nullptr, qh, ql, M, Dd, Dd, 0);
    launch_gemm_t(gemm_bf<0,0,1>, xh, xl, wh+1*WSZ, wl+1*WSZ, sa_bk, nullptr, nullptr, kh, kl, M, Dd, Dd, 0);
    launch_gemm_t(gemm_bf<0,0,2>, xh, xl, wh+2*WSZ, wl+2*WSZ, sa_bv, nullptr, nullptr, vth, vtl, M, Dd, Dd, MTOT);
    attn_mma<<<agrid, 128, ASMEM>>>(qh, ql, kh, kl, vth, vtl, cth, ctl, Ss, Ss, Ss, MTOT, 1);
    launch_gemm_t(gemm_bf<0,1,0>, cth, ctl, wh+3*WSZ, wl+3*WSZ, sa_bo, X, t1, nullptr, nullptr, M, Dd, Dd, 0);
    ln_kernel<<<M, 256>>>(t1, sa_lg, sa_lb, x1, x1h, x1l);

    // ---- cross-attention ----
    launch_gemm_t(gemm_bf<0,0,1>, x1h, x1l, wh+4*WSZ, wl+4*WSZ, ca_bq, nullptr, nullptr, qh, ql, M, Dd, Dd, 0);
    launch_gemm_t(gemm_bf<0,0,1>, tgh, tgl, wh+5*WSZ, wl+5*WSZ, ca_bk, nullptr, nullptr, ckh, ckl, Tt, Dd, Dd, 0);
    launch_gemm_t(gemm_bf<0,0,2>, tgh, tgl, wh+6*WSZ, wl+6*WSZ, ca_bv, nullptr, nullptr, cvth, cvtl, Tt, Dd, Dd, Tt);
    attn_mma<<<agrid, 128, ASMEM>>>(qh, ql, ckh, ckl, cvth, cvtl, cth, ctl, Tt, 0, 0, Tt, 0);
    launch_gemm_t(gemm_bf<0,1,0>, cth, ctl, wh+7*WSZ, wl+7*WSZ, ca_bo, x1, t1, nullptr, nullptr, M, Dd, Dd, 0);
    ln_kernel<<<M, 256>>>(t1, ca_lg, ca_lb, x2, x2h, x2l);

    // ---- FFN ----
    launch_gemm_t(gemm_bf<1,0,1>, x2h, x2l, wh+WOFF_FF1, wl+WOFF_FF1, ff_b1, nullptr, nullptr, ffh, ffl, M, FFd, Dd, 0);
    launch_gemm_t(gemm_bf<0,1,0>, ffh, ffl, wh+WOFF_FF2, wl+WOFF_FF2, ff_b2, x2, t1, nullptr, nullptr, M, Dd, FFd, 0);
    ln_kernel<<<M, 256>>>(t1, ff_lg, ff_lb, out, nullptr, nullptr);
}

// round 9
// speedup vs baseline: 2.7391x; 1.1228x over previous
#include <cuda_runtime.h>
#include <cuda_bf16.h>
#include <math.h>
#include <cstdint>

// Problem constants
#define Bb   2
#define Ss   2048
#define Dd   768
#define Hh   12
#define DHd  64
#define Tt   64
#define FFd  3072
#define Rr   50

#define MTOT (Bb*Ss)        // 4096

// ---------------- scratch (device globals; no allocations allowed) ----------
__device__ float g_t1 [MTOT*Dd];
__device__ float g_x1 [MTOT*Dd];
__device__ float g_x2 [MTOT*Dd];

// bf16 hi/lo buffers
__device__ __nv_bfloat16 g_xh [MTOT*Dd],  g_xl [MTOT*Dd];
__device__ __nv_bfloat16 g_x1h[MTOT*Dd],  g_x1l[MTOT*Dd];
__device__ __nv_bfloat16 g_x2h[MTOT*Dd],  g_x2l[MTOT*Dd];
__device__ __nv_bfloat16 g_cth[MTOT*Dd],  g_ctl[MTOT*Dd];
__device__ __nv_bfloat16 g_ffh[MTOT*FFd], g_ffl[MTOT*FFd];
__device__ __nv_bfloat16 g_tgh[Tt*Dd],    g_tgl[Tt*Dd];
__device__ __nv_bfloat16 g_qh [MTOT*Dd],  g_ql [MTOT*Dd];
__device__ __nv_bfloat16 g_kh [MTOT*Dd],  g_kl [MTOT*Dd];
__device__ __nv_bfloat16 g_vth[Dd*MTOT],  g_vtl[Dd*MTOT];   // V^T [n][m]
__device__ __nv_bfloat16 g_ckh[Tt*Dd],    g_ckl[Tt*Dd];
__device__ __nv_bfloat16 g_cvth[Dd*Tt],   g_cvtl[Dd*Tt];    // cross V^T

// transposed weights [N][K] hi/lo
#define WSZ  (Dd*Dd)
#define WOFF_FF1 (8*WSZ)
#define WOFF_FF2 (WOFF_FF1 + Dd*FFd)
#define WTOT (WOFF_FF2 + FFd*Dd)
__device__ __nv_bfloat16 g_wh[WTOT], g_wl[WTOT];

// =============== helpers =====================================================
__device__ __forceinline__ void mma16816(float* c, const uint32_t* a, const uint32_t* b) {
    asm volatile(
        "mma.sync.aligned.m16n8k16.row.col.f32.bf16.bf16.f32 "
        "{%0,%1,%2,%3}, {%4,%5,%6,%7}, {%8,%9}, {%0,%1,%2,%3};\n"
        : "+f"(c[0]), "+f"(c[1]), "+f"(c[2]), "+f"(c[3])
        : "r"(a[0]), "r"(a[1]), "r"(a[2]), "r"(a[3]), "r"(b[0]), "r"(b[1]));
}
__device__ __forceinline__ void ldsm4(uint32_t* r, uint32_t addr) {
    asm volatile("ldmatrix.sync.aligned.m8n8.x4.shared.b16 {%0,%1,%2,%3}, [%4];"
                 : "=r"(r[0]), "=r"(r[1]), "=r"(r[2]), "=r"(r[3]) : "r"(addr));
}
__device__ __forceinline__ uint32_t pack_bf2(__nv_bfloat16 a, __nv_bfloat16 b) {
    return ((uint32_t)__bfloat16_as_ushort(b) << 16) | (uint32_t)__bfloat16_as_ushort(a);
}
__device__ __forceinline__ uint32_t smem_u32(const void* p) {
    uint32_t a;
    asm("{ .reg .u64 t; cvta.to.shared.u64 t, %1; cvt.u32.u64 %0, t; }" : "=r"(a) : "l"(p));
    return a;
}
__device__ __forceinline__ void cpa16(uint32_t dst, const void* src, bool valid) {
    int sz = valid ? 16 : 0;
    asm volatile("cp.async.cg.shared.global [%0], [%1], 16, %2;"
                 :: "r"(dst), "l"(src), "r"(sz));
}
#define CP_COMMIT() asm volatile("cp.async.commit_group;" ::: "memory")
#define CP_WAIT(n)  asm volatile("cp.async.wait_group %0;" :: "n"(n) : "memory")

__device__ __forceinline__ void split_bf(float v, __nv_bfloat16& h, __nv_bfloat16& l) {
    h = __float2bfloat16(v);
    l = __float2bfloat16(v - __bfloat162float(h));
}

// ============ conversion kernels ============================================
__global__ void fconv(const float* __restrict__ x, __nv_bfloat16* __restrict__ h,
                      __nv_bfloat16* __restrict__ l, int n4)
{
    int i = blockIdx.x * 256 + threadIdx.x;
    if (i >= n4) return;
    float4 v = ((const float4*)x)[i];
    __nv_bfloat16 h0,h1,h2,h3,l0,l1,l2,l3;
    split_bf(v.x,h0,l0); split_bf(v.y,h1,l1); split_bf(v.z,h2,l2); split_bf(v.w,h3,l3);
    ((uint2*)h)[i] = make_uint2(pack_bf2(h0,h1), pack_bf2(h2,h3));
    ((uint2*)l)[i] = make_uint2(pack_bf2(l0,l1), pack_bf2(l2,l3));
}

// fused weight transpose+split for all 10 weights in one launch
struct WAll {
    const float* W[10];
    __nv_bfloat16* Wh[10];
    __nv_bfloat16* Wl[10];
    int K[10], N[10], t0[10];
};

__global__ void wtconv_all(WAll d)
{
    __shared__ float t[32][33];
    const int bid = blockIdx.x;
    int w = 0;
    #pragma unroll
    for (int i = 1; i < 10; i++) if (bid >= d.t0[i]) w = i;
    const int K = d.K[w], N = d.N[w];
    const int tloc = bid - d.t0[w];
    const int nx = N >> 5;
    const int n0 = (tloc % nx) * 32, k0 = (tloc / nx) * 32;
    const float* W = d.W[w];
    __nv_bfloat16* Wh = d.Wh[w];
    __nv_bfloat16* Wl = d.Wl[w];

    const int tx = threadIdx.x, ty = threadIdx.y;   // 32 x 8
    #pragma unroll
    for (int i = 0; i < 4; i++)
        t[ty + i*8][tx] = W[(long)(k0 + ty + i*8) * N + n0 + tx];
    __syncthreads();
    #pragma unroll
    for (int i = 0; i < 4; i++) {
        int n = n0 + ty + i*8;
        float v = t[tx][ty + i*8];
        __nv_bfloat16 h, l; split_bf(v, h, l);
        Wh[(long)n * K + k0 + tx] = h;
        Wl[(long)n * K + k0 + tx] = l;
    }
}

// ======== split-bf16 tensor-core GEMM ========================================
// OMODE: 0 = fp32 C, 1 = bf16 hi/lo, 2 = bf16 hi/lo TRANSPOSED [n][m] (ldt)
#define STG_B 40960

template<int ACT, int RES, int OMODE>
__global__ void __launch_bounds__(256)
gemm_bf(const __nv_bfloat16* __restrict__ Ahp, const __nv_bfloat16* __restrict__ Alp,
        const __nv_bfloat16* __restrict__ Bhp, const __nv_bfloat16* __restrict__ Blp,
        const float* __restrict__ bias, const float* __restrict__ Rz,
        float* __restrict__ C, __nv_bfloat16* __restrict__ Chp, __nv_bfloat16* __restrict__ Clp,
        int M, int N, int K, int ldt)
{
    extern __shared__ char smem[];
    const uint32_t sb = smem_u32(smem);
    const int tid  = threadIdx.x;
    const int wid  = tid >> 5;
    const int lane = tid & 31;
    const int wm   = (wid & 1) * 64;
    const int wn   = (wid >> 1) * 32;
    const int bm   = blockIdx.y * 128;
    const int bn   = blockIdx.x * 128;
    const int nch  = K >> 5;
    const int gq = lane >> 2;
    const int gt = lane & 3;

    // ldmatrix per-lane offsets (row stride 80B)
    const int lrow = lane & 7, lmat = lane >> 3;
    const uint32_t aoff = (uint32_t)((lrow + (lmat & 1) * 8) * 80 + (lmat >> 1) * 16);
    const uint32_t boff = (uint32_t)((lrow + (lmat >> 1) * 8) * 80 + (lmat & 1) * 16);

    float acc[4][4][4];
    #pragma unroll
    for (int i = 0; i < 4; i++)
        #pragma unroll
        for (int j = 0; j < 4; j++)
            #pragma unroll
            for (int e = 0; e < 4; e++) acc[i][j][e] = 0.f;

    const __nv_bfloat16* srcs[4] = {Ahp, Alp, Bhp, Blp};

    auto load_stage = [&](int s, int k0) {
        #pragma unroll
        for (int a = 0; a < 4; a++) {
            #pragma unroll
            for (int t = 0; t < 2; t++) {
                int q   = tid + t * 256;
                int row = q >> 2, c4 = q & 3;
                int grow = (a < 2) ? (bm + row) : (bn + row);
                bool valid = (a < 2) ? (grow < M) : true;
                const __nv_bfloat16* src = srcs[a] + (long)(valid ? grow : 0) * K + k0 + c4 * 8;
                cpa16(sb + s * STG_B + a * 10240 + row * 80 + c4 * 16, src, valid);
            }
        }
    };

    load_stage(0, 0);
    CP_COMMIT();

    for (int c = 0; c < nch; c++) {
        if (c + 1 < nch) { load_stage((c + 1) & 1, (c + 1) * 32); CP_COMMIT(); CP_WAIT(1); }
        else             { CP_WAIT(0); }
        __syncthreads();

        const uint32_t stb = sb + (c & 1) * STG_B;
        const uint32_t sAh = stb, sAl = stb + 10240, sBh = stb + 20480, sBl = stb + 30720;

        #pragma unroll
        for (int ks = 0; ks < 2; ks++) {
            const uint32_t kof = ks * 32;
            uint32_t bh[4][2], bl[4][2];
            #pragma unroll
            for (int jp = 0; jp < 2; jp++) {
                uint32_t ad = (uint32_t)((wn + jp * 16) * 80) + kof;
                ldsm4(&bh[jp*2][0], sBh + ad + boff);
                ldsm4(&bl[jp*2][0], sBl + ad + boff);
            }
            #pragma unroll
            for (int i = 0; i < 4; i++) {
                uint32_t ad = (uint32_t)((wm + i * 16) * 80) + kof;
                uint32_t ahf[4], alf[4];
                ldsm4(ahf, sAh + ad + aoff);
                ldsm4(alf, sAl + ad + aoff);
                #pragma unroll
                for (int j = 0; j < 4; j++) {
                    mma16816(acc[i][j], ahf, bh[j]);
                    mma16816(acc[i][j], alf, bh[j]);
                    mma16816(acc[i][j], ahf, bl[j]);
                }
            }
        }
        __syncthreads();
    }

    #pragma unroll
    for (int i = 0; i < 4; i++) {
        #pragma unroll
        for (int rr = 0; rr < 2; rr++) {
            int m = bm + wm + i * 16 + gq + rr * 8;
            if (m >= M) continue;
            #pragma unroll
            for (int j = 0; j < 4; j++) {
                int n = bn + wn + j * 8 + gt * 2;
                float v0 = acc[i][j][rr * 2 + 0] + __ldg(&bias[n]);
                float v1 = acc[i][j][rr * 2 + 1] + __ldg(&bias[n + 1]);
                if (RES) {
                    const float* rp = Rz + (long)m * N + n;
                    v0 += rp[0]; v1 += rp[1];
                }
                if (ACT) {
                    v0 = 0.5f * v0 * (1.0f + erff(v0 * 0.70710678118654752f));
                    v1 = 0.5f * v1 * (1.0f + erff(v1 * 0.70710678118654752f));
                }
                if (OMODE == 0)
                    *(float2*)(C + (long)m * N + n) = make_float2(v0, v1);
                if (OMODE == 1) {
                    __nv_bfloat16 h0,h1,l0,l1;
                    split_bf(v0,h0,l0); split_bf(v1,h1,l1);
                    *(uint32_t*)(Chp + (long)m * N + n) = pack_bf2(h0,h1);
                    *(uint32_t*)(Clp + (long)m * N + n) = pack_bf2(l0,l1);
                }
                if (OMODE == 2) {
                    __nv_bfloat16 h0,h1,l0,l1;
                    split_bf(v0,h0,l0); split_bf(v1,h1,l1);
                    Chp[(long)n * ldt + m]       = h0;
                    Chp[(long)(n + 1) * ldt + m] = h1;
                    Clp[(long)n * ldt + m]       = l0;
                    Clp[(long)(n + 1) * ldt + m] = l1;
                }
            }
        }
    }
}

// ============ tensor-core flash attention (split bf16) =======================
#define ATS   144
#define AROWB 9216
#define ASTG0 (2*AROWB)
#define ASTGSZ (4*AROWB)
#define ASMEM (ASTG0 + 2*ASTGSZ)  // 92160

__global__ void __launch_bounds__(128)
attn_mma(const __nv_bfloat16* __restrict__ Qh, const __nv_bfloat16* __restrict__ Ql,
         const __nv_bfloat16* __restrict__ Kh, const __nv_bfloat16* __restrict__ Kl,
         const __nv_bfloat16* __restrict__ Vth, const __nv_bfloat16* __restrict__ Vtl,
         __nv_bfloat16* __restrict__ Oh, __nv_bfloat16* __restrict__ Ol,
         int Sk, int kvRowPB, int vtColPB, int ldv, int band)
{
    extern __shared__ char sm[];
    const uint32_t sb = smem_u32(sm);
    const int tid = threadIdx.x;
    const int wq  = tid >> 5;
    const int lane = tid & 31;
    const int gq = lane >> 2, gt = lane & 3;
    const int b = blockIdx.z, h = blockIdx.y, q0 = blockIdx.x * 64;

    const int lrow = lane & 7, lmat = lane >> 3;
    const uint32_t aoffA = (uint32_t)((lrow + (lmat & 1) * 8) * ATS + (lmat >> 1) * 16);
    const uint32_t boffA = (uint32_t)((lrow + (lmat >> 1) * 8) * ATS + (lmat & 1) * 16);

    // Q tile (loaded once)
    {
        const __nv_bfloat16* qsrc[2] = {Qh, Ql};
        #pragma unroll
        for (int a = 0; a < 2; a++) {
            const __nv_bfloat16* src = qsrc[a] + ((long)(b * Ss + q0)) * Dd + h * DHd;
            #pragma unroll
            for (int it = 0; it < 4; it++) {
                int idx = it * 128 + tid, row = idx >> 3, c4 = idx & 7;
                cpa16(sb + a * AROWB + row * ATS + c4 * 16, src + (long)row * Dd + c4 * 8, true);
            }
        }
    }
    auto loadKV = [&](int stg, int k0) {
        uint32_t so = sb + ASTG0 + (stg & 1) * ASTGSZ;
        const __nv_bfloat16* ks[2] = {Kh, Kl};
        #pragma unroll
        for (int a = 0; a < 2; a++) {
            const __nv_bfloat16* src = ks[a] + ((long)(kvRowPB * b + k0)) * Dd + h * DHd;
            #pragma unroll
            for (int it = 0; it < 4; it++) {
                int idx = it * 128 + tid, row = idx >> 3, c4 = idx & 7;
                cpa16(so + a * AROWB + row * ATS + c4 * 16, src + (long)row * Dd + c4 * 8, true);
            }
        }
        const __nv_bfloat16* vs[2] = {Vth, Vtl};
        #pragma unroll
        for (int a = 0; a < 2; a++) {
            const __nv_bfloat16* src = vs[a] + (long)(h * DHd) * ldv + (long)vtColPB * b + k0;
            #pragma unroll
            for (int it = 0; it < 4; it++) {
                int idx = it * 128 + tid, row = idx >> 3, c4 = idx & 7;
                cpa16(so + (2 + a) * AROWB + row * ATS + c4 * 16, src + (long)row * ldv + c4 * 8, true);
            }
        }
    };
    loadKV(0, 0);
    CP_COMMIT();

    float m0 = -1e30f, m1 = -1e30f, l0 = 0.f, l1 = 0.f;
    float o[8][4];
    #pragma unroll
    for (int j = 0; j < 8; j++)
        #pragma unroll
        for (int e = 0; e < 4; e++) o[j][e] = 0.f;
    uint32_t qfh[4][4], qfl[4][4];

    const int nkt = Sk >> 6;
    for (int t = 0; t < nkt; t++) {
        if (t + 1 < nkt) { loadKV(t + 1, (t + 1) * 64); CP_COMMIT(); CP_WAIT(1); }
        else             { CP_WAIT(0); }
        __syncthreads();

        if (t == 0) {
            const uint32_t qb0 = sb + (uint32_t)(wq * 16 * ATS);
            #pragma unroll
            for (int s = 0; s < 4; s++) {
                ldsm4(qfh[s], qb0 + s * 32 + aoffA);
                ldsm4(qfl[s], qb0 + AROWB + s * 32 + aoffA);
            }
        }

        const uint32_t stb = sb + ASTG0 + (t & 1) * ASTGSZ;
        const uint32_t sKh = stb, sKl = stb + AROWB;
        const uint32_t sVh = stb + 2 * AROWB, sVl = stb + 3 * AROWB;

        // ---- scores S = Q K^T ----
        float sc[8][4];
        #pragma unroll
        for (int j = 0; j < 8; j++)
            #pragma unroll
            for (int e = 0; e < 4; e++) sc[j][e] = 0.f;

        #pragma unroll
        for (int jp = 0; jp < 4; jp++) {
            uint32_t ad = (uint32_t)(jp * 16 * ATS);
            #pragma unroll
            for (int s = 0; s < 4; s++) {
                uint32_t kh4[4], kl4[4];
                ldsm4(kh4, sKh + ad + s * 32 + boffA);
                ldsm4(kl4, sKl + ad + s * 32 + boffA);
                mma16816(sc[2*jp],   qfh[s], &kh4[0]);
                mma16816(sc[2*jp],   qfl[s], &kh4[0]);
                mma16816(sc[2*jp],   qfh[s], &kl4[0]);
                mma16816(sc[2*jp+1], qfh[s], &kh4[2]);
                mma16816(sc[2*jp+1], qfl[s], &kh4[2]);
                mma16816(sc[2*jp+1], qfh[s], &kl4[2]);
            }
        }

        const int k0 = t * 64;
        const int qi0 = q0 + wq * 16 + gq, qi1 = qi0 + 8;
        #pragma unroll
        for (int j = 0; j < 8; j++) {
            int ki0 = k0 + j * 8 + gt * 2, ki1 = ki0 + 1;
            if (band) {
                int d00 = qi0 - ki0; d00 = d00 < 0 ? -d00 : d00;
                int d01 = qi0 - ki1; d01 = d01 < 0 ? -d01 : d01;
                int d10 = qi1 - ki0; d10 = d10 < 0 ? -d10 : d10;
                int d11 = qi1 - ki1; d11 = d11 < 0 ? -d11 : d11;
                sc[j][0] = sc[j][0] * 0.125f + (d00 <= Rr ? 1.f : 0.f);
                sc[j][1] = sc[j][1] * 0.125f + (d01 <= Rr ? 1.f : 0.f);
                sc[j][2] = sc[j][2] * 0.125f + (d10 <= Rr ? 1.f : 0.f);
                sc[j][3] = sc[j][3] * 0.125f + (d11 <= Rr ? 1.f : 0.f);
            } else {
                sc[j][0] *= 0.125f; sc[j][1] *= 0.125f;
                sc[j][2] *= 0.125f; sc[j][3] *= 0.125f;
            }
        }

        // ---- online softmax ----
        float nm0 = -1e30f, nm1 = -1e30f;
        #pragma unroll
        for (int j = 0; j < 8; j++) {
            nm0 = fmaxf(nm0, fmaxf(sc[j][0], sc[j][1]));
            nm1 = fmaxf(nm1, fmaxf(sc[j][2], sc[j][3]));
        }
        nm0 = fmaxf(nm0, __shfl_xor_sync(0xffffffffu, nm0, 1));
        nm0 = fmaxf(nm0, __shfl_xor_sync(0xffffffffu, nm0, 2));
        nm1 = fmaxf(nm1, __shfl_xor_sync(0xffffffffu, nm1, 1));
        nm1 = fmaxf(nm1, __shfl_xor_sync(0xffffffffu, nm1, 2));
        float M0 = fmaxf(m0, nm0), M1 = fmaxf(m1, nm1);
        float f0 = __expf(m0 - M0), f1 = __expf(m1 - M1);
        m0 = M0; m1 = M1;

        float s0 = 0.f, s1 = 0.f;
        #pragma unroll
        for (int j = 0; j < 8; j++) {
            sc[j][0] = __expf(sc[j][0] - M0);
            sc[j][1] = __expf(sc[j][1] - M0);
            sc[j][2] = __expf(sc[j][2] - M1);
            sc[j][3] = __expf(sc[j][3] - M1);
            s0 += sc[j][0] + sc[j][1];
            s1 += sc[j][2] + sc[j][3];
        }
        s0 += __shfl_xor_sync(0xffffffffu, s0, 1);
        s0 += __shfl_xor_sync(0xffffffffu, s0, 2);
        s1 += __shfl_xor_sync(0xffffffffu, s1, 1);
        s1 += __shfl_xor_sync(0xffffffffu, s1, 2);
        l0 = l0 * f0 + s0;
        l1 = l1 * f1 + s1;

        #pragma unroll
        for (int j = 0; j < 8; j++) {
            o[j][0] *= f0; o[j][1] *= f0;
            o[j][2] *= f1; o[j][3] *= f1;
        }

        // ---- P fragments (bf16 hi/lo) ----
        uint32_t ph[4][4], pl[4][4];
        #pragma unroll
        for (int s = 0; s < 4; s++) {
            __nv_bfloat16 h0,h1,lo0,lo1;
            split_bf(sc[2*s][0], h0, lo0); split_bf(sc[2*s][1], h1, lo1);
            ph[s][0] = pack_bf2(h0,h1); pl[s][0] = pack_bf2(lo0,lo1);
            split_bf(sc[2*s][2], h0, lo0); split_bf(sc[2*s][3], h1, lo1);
            ph[s][1] = pack_bf2(h0,h1); pl[s][1] = pack_bf2(lo0,lo1);
            split_bf(sc[2*s+1][0], h0, lo0); split_bf(sc[2*s+1][1], h1, lo1);
            ph[s][2] = pack_bf2(h0,h1); pl[s][2] = pack_bf2(lo0,lo1);
            split_bf(sc[2*s+1][2], h0, lo0); split_bf(sc[2*s+1][3], h1, lo1);
            ph[s][3] = pack_bf2(h0,h1); pl[s][3] = pack_bf2(lo0,lo1);
        }

        // ---- O += P V ----
        #pragma unroll
        for (int jp = 0; jp < 4; jp++) {
            uint32_t ad = (uint32_t)(jp * 16 * ATS);
            #pragma unroll
            for (int s = 0; s < 4; s++) {
                uint32_t vh4[4], vl4[4];
                ldsm4(vh4, sVh + ad + s * 32 + boffA);
                ldsm4(vl4, sVl + ad + s * 32 + boffA);
                mma16816(o[2*jp],   ph[s], &vh4[0]);
                mma16816(o[2*jp],   pl[s], &vh4[0]);
                mma16816(o[2*jp],   ph[s], &vl4[0]);
                mma16816(o[2*jp+1], ph[s], &vh4[2]);
                mma16816(o[2*jp+1], pl[s], &vh4[2]);
                mma16816(o[2*jp+1], ph[s], &vl4[2]);
            }
        }
        __syncthreads();
    }

    // ---- write ctx as bf16 hi/lo ----
    float i0 = 1.f / l0, i1 = 1.f / l1;
    long r0g = (long)(b * Ss) + q0 + wq * 16 + gq;
    #pragma unroll
    for (int jd = 0; jd < 8; jd++) {
        int col = h * DHd + jd * 8 + gt * 2;
        float v0 = o[jd][0] * i0, v1 = o[jd][1] * i0;
        float v2 = o[jd][2] * i1, v3 = o[jd][3] * i1;
        __nv_bfloat16 h0,h1,lo0,lo1;
        split_bf(v0,h0,lo0); split_bf(v1,h1,lo1);
        *(uint32_t*)(Oh + r0g * Dd + col) = pack_bf2(h0,h1);
        *(uint32_t*)(Ol + r0g * Dd + col) = pack_bf2(lo0,lo1);
        split_bf(v2,h0,lo0); split_bf(v3,h1,lo1);
        *(uint32_t*)(Oh + (r0g + 8) * Dd + col) = pack_bf2(h0,h1);
        *(uint32_t*)(Ol + (r0g + 8) * Dd + col) = pack_bf2(lo0,lo1);
    }
}

// ---------------- LayerNorm ---------------------------------------------
__global__ __launch_bounds__(256)
void ln_kernel(const float* __restrict__ in, const float* __restrict__ g,
               const float* __restrict__ bta, float* __restrict__ out,
               __nv_bfloat16* __restrict__ oh, __nv_bfloat16* __restrict__ ol)
{
    const int row = blockIdx.x;
    const float* x = in + (long)row * Dd;
    const int tid = threadIdx.x;

    float v0 = x[tid], v1 = x[tid + 256], v2 = x[tid + 512];
    float s = v0 + v1 + v2;

    __shared__ float sred[8];
    __shared__ float smean, svar;

    #pragma unroll
    for (int off = 16; off; off >>= 1) s += __shfl_xor_sync(0xffffffffu, s, off);
    if ((tid & 31) == 0) sred[tid >> 5] = s;
    __syncthreads();
    if (tid == 0) {
        float t = 0.f;
        #pragma unroll
        for (int i = 0; i < 8; i++) t += sred[i];
        smean = t * (1.0f / Dd);
    }
    __syncthreads();
    float m = smean;
    float d0 = v0 - m, d1 = v1 - m, d2 = v2 - m;
    float sq = d0*d0 + d1*d1 + d2*d2;
    #pragma unroll
    for (int off = 16; off; off >>= 1) sq += __shfl_xor_sync(0xffffffffu, sq, off);
    if ((tid & 31) == 0) sred[tid >> 5] = sq;
    __syncthreads();
    if (tid == 0) {
        float t = 0.f;
        #pragma unroll
        for (int i = 0; i < 8; i++) t += sred[i];
        svar = t * (1.0f / Dd);
    }
    __syncthreads();
    float inv = rsqrtf(svar + 1e-12f);
    #pragma unroll
    for (int u = 0; u < 3; u++) {
        int idx = tid + u * 256;
        float d = (u == 0 ? d0 : (u == 1 ? d1 : d2));
        float val = d * inv * g[idx] + bta[idx];
        out[(long)row * Dd + idx] = val;
        if (oh) {
            __nv_bfloat16 hh, ll; split_bf(val, hh, ll);
            oh[(long)row * Dd + idx] = hh;
            ol[(long)row * Dd + idx] = ll;
        }
    }
}

// ---------------- launch ----------------------------------------------------
typedef void (*gemm_fn)(const __nv_bfloat16*, const __nv_bfloat16*,
                        const __nv_bfloat16*, const __nv_bfloat16*,
                        const float*, const float*,
                        float*, __nv_bfloat16*, __nv_bfloat16*, int, int, int, int);

static inline void launch_gemm_t(gemm_fn fn,
                                 const __nv_bfloat16* Ah, const __nv_bfloat16* Al,
                                 const __nv_bfloat16* Bh, const __nv_bfloat16* Bl,
                                 const float* bias, const float* Rz,
                                 float* C, __nv_bfloat16* Ch, __nv_bfloat16* Cl,
                                 int M, int N, int K, int ldt)
{
    dim3 g(N / 128, (M + 127) / 128);
    cudaFuncSetAttribute((const void*)fn, cudaFuncAttributeMaxDynamicSharedMemorySize, 2 * STG_B);
    fn<<<g, 256, 2 * STG_B>>>(Ah, Al, Bh, Bl, bias, Rz, C, Ch, Cl, M, N, K, ldt);
}

extern "C" void kernel_launch(void* const* d_in, const int* in_sizes, int n_in,
                              void* d_out, int out_size)
{
    const float* X     = (const float*)d_in[0];
    const float* tag   = (const float*)d_in[1];
    const float* sa_wq = (const float*)d_in[2];  const float* sa_bq = (const float*)d_in[3];
    const float* sa_wk = (const float*)d_in[4];  const float* sa_bk = (const float*)d_in[5];
    const float* sa_wv = (const float*)d_in[6];  const float* sa_bv = (const float*)d_in[7];
    const float* sa_wo = (const float*)d_in[8];  const float* sa_bo = (const float*)d_in[9];
    const float* sa_lg = (const float*)d_in[10]; const float* sa_lb = (const float*)d_in[11];
    const float* ca_wq = (const float*)d_in[12]; const float* ca_bq = (const float*)d_in[13];
    const float* ca_wk = (const float*)d_in[14]; const float* ca_bk = (const float*)d_in[15];
    const float* ca_wv = (const float*)d_in[16]; const float* ca_bv = (const float*)d_in[17];
    const float* ca_wo = (const float*)d_in[18]; const float* ca_bo = (const float*)d_in[19];
    const float* ca_lg = (const float*)d_in[20]; const float* ca_lb = (const float*)d_in[21];
    const float* ff_w1 = (const float*)d_in[22]; const float* ff_b1 = (const float*)d_in[23];
    const float* ff_w2 = (const float*)d_in[24]; const float* ff_b2 = (const float*)d_in[25];
    const float* ff_lg = (const float*)d_in[26]; const float* ff_lb = (const float*)d_in[27];
    float* out = (float*)d_out;

    float *t1, *x1, *x2;
    cudaGetSymbolAddress((void**)&t1, g_t1);
    cudaGetSymbolAddress((void**)&x1, g_x1); cudaGetSymbolAddress((void**)&x2, g_x2);

    __nv_bfloat16 *xh,*xl,*x1h,*x1l,*x2h,*x2l,*cth,*ctl,*ffh,*ffl,*tgh,*tgl,*wh,*wl;
    __nv_bfloat16 *qh,*ql,*kh,*kl,*vth,*vtl,*ckh,*ckl,*cvth,*cvtl;
    cudaGetSymbolAddress((void**)&xh,  g_xh);  cudaGetSymbolAddress((void**)&xl,  g_xl);
    cudaGetSymbolAddress((void**)&x1h, g_x1h); cudaGetSymbolAddress((void**)&x1l, g_x1l);
    cudaGetSymbolAddress((void**)&x2h, g_x2h); cudaGetSymbolAddress((void**)&x2l, g_x2l);
    cudaGetSymbolAddress((void**)&cth, g_cth); cudaGetSymbolAddress((void**)&ctl, g_ctl);
    cudaGetSymbolAddress((void**)&ffh, g_ffh); cudaGetSymbolAddress((void**)&ffl, g_ffl);
    cudaGetSymbolAddress((void**)&tgh, g_tgh); cudaGetSymbolAddress((void**)&tgl, g_tgl);
    cudaGetSymbolAddress((void**)&wh,  g_wh);  cudaGetSymbolAddress((void**)&wl,  g_wl);
    cudaGetSymbolAddress((void**)&qh,  g_qh);  cudaGetSymbolAddress((void**)&ql,  g_ql);
    cudaGetSymbolAddress((void**)&kh,  g_kh);  cudaGetSymbolAddress((void**)&kl,  g_kl);
    cudaGetSymbolAddress((void**)&vth, g_vth); cudaGetSymbolAddress((void**)&vtl, g_vtl);
    cudaGetSymbolAddress((void**)&ckh, g_ckh); cudaGetSymbolAddress((void**)&ckl, g_ckl);
    cudaGetSymbolAddress((void**)&cvth,g_cvth);cudaGetSymbolAddress((void**)&cvtl,g_cvtl);

    const int M = MTOT;
    dim3 agrid(Ss / 64, Hh, Bb);
    dim3 tb(32, 8);

    cudaFuncSetAttribute(attn_mma, cudaFuncAttributeMaxDynamicSharedMemorySize, ASMEM);

    // ---- pre-convert activations & weights ----
    fconv<<<(M*Dd/4 + 255)/256, 256>>>(X, xh, xl, M*Dd/4);
    fconv<<<(Tt*Dd/4 + 255)/256, 256>>>(tag, tgh, tgl, Tt*Dd/4);

    {
        const float* ws[10]  = {sa_wq, sa_wk, sa_wv, sa_wo, ca_wq, ca_wk, ca_wv, ca_wo, ff_w1, ff_w2};
        const long  woff[10] = {0, WSZ, 2*WSZ, 3*WSZ, 4*WSZ, 5*WSZ, 6*WSZ, 7*WSZ, WOFF_FF1, WOFF_FF2};
        const int   wk_[10]  = {Dd,Dd,Dd,Dd,Dd,Dd,Dd,Dd,Dd,FFd};
        const int   wn_[10]  = {Dd,Dd,Dd,Dd,Dd,Dd,Dd,Dd,FFd,Dd};
        WAll wa;
        int cum = 0;
        for (int i = 0; i < 10; i++) {
            wa.W[i] = ws[i]; wa.Wh[i] = wh + woff[i]; wa.Wl[i] = wl + woff[i];
            wa.K[i] = wk_[i]; wa.N[i] = wn_[i]; wa.t0[i] = cum;
            cum += (wk_[i] / 32) * (wn_[i] / 32);
        }
        wtconv_all<<<cum, tb>>>(wa);
    }

    // ---- self-attention ----
    launch_gemm_t(gemm_bf<0,0,1>, xh, xl, wh+0*WSZ, wl+0*WSZ, sa_bq, nullptr, nullptr, qh, ql, M, Dd, Dd, 0);
    launch_gemm_t(gemm_bf<0,0,1>, xh, xl, wh+1*WSZ, wl+1*WSZ, sa_bk, nullptr, nullptr, kh, kl, M, Dd, Dd, 0);
    launch_gemm_t(gemm_bf<0,0,2>, xh, xl, wh+2*WSZ, wl+2*WSZ, sa_bv, nullptr, nullptr, vth, vtl, M, Dd, Dd, MTOT);
    attn_mma<<<agrid, 128, ASMEM>>>(qh, ql, kh, kl, vth, vtl, cth, ctl, Ss, Ss, Ss, MTOT, 1);
    launch_gemm_t(gemm_bf<0,1,0>, cth, ctl, wh+3*WSZ, wl+3*WSZ, sa_bo, X, t1, nullptr, nullptr, M, Dd, Dd, 0);
    ln_kernel<<<M, 256>>>(t1, sa_lg, sa_lb, x1, x1h, x1l);

    // ---- cross-attention ----
    launch_gemm_t(gemm_bf<0,0,1>, x1h, x1l, wh+4*WSZ, wl+4*WSZ, ca_bq, nullptr, nullptr, qh, ql, M, Dd, Dd, 0);
    launch_gemm_t(gemm_bf<0,0,1>, tgh, tgl, wh+5*WSZ, wl+5*WSZ, ca_bk, nullptr, nullptr, ckh, ckl, Tt, Dd, Dd, 0);
    launch_gemm_t(gemm_bf<0,0,2>, tgh, tgl, wh+6*WSZ, wl+6*WSZ, ca_bv, nullptr, nullptr, cvth, cvtl, Tt, Dd, Dd, Tt);
    attn_mma<<<agrid, 128, ASMEM>>>(qh, ql, ckh, ckl, cvth, cvtl, cth, ctl, Tt, 0, 0, Tt, 0);
    launch_gemm_t(gemm_bf<0,1,0>, cth, ctl, wh+7*WSZ, wl+7*WSZ, ca_bo, x1, t1, nullptr, nullptr, M, Dd, Dd, 0);
    ln_kernel<<<M, 256>>>(t1, ca_lg, ca_lb, x2, x2h, x2l);

    // ---- FFN ----
    launch_gemm_t(gemm_bf<1,0,1>, x2h, x2l, wh+WOFF_FF1, wl+WOFF_FF1, ff_b1, nullptr, nullptr, ffh, ffl, M, FFd, Dd, 0);
    launch_gemm_t(gemm_bf<0,1,0>, ffh, ffl, wh+WOFF_FF2, wl+WOFF_FF2, ff_b2, x2, t1, nullptr, nullptr, M, Dd, FFd, 0);
    ln_kernel<<<M, 256>>>(t1, ff_lg, ff_lb, out, nullptr, nullptr);
}

// round 10
// speedup vs baseline: 2.8958x; 1.0572x over previous
#include <cuda_runtime.h>
#include <cuda_bf16.h>
#include <math.h>
#include <cstdint>

// Problem constants
#define Bb   2
#define Ss   2048
#define Dd   768
#define Hh   12
#define DHd  64
#define Tt   64
#define FFd  3072
#define Rr   50

#define MTOT (Bb*Ss)        // 4096

// ---------------- scratch (device globals; no allocations allowed) ----------
__device__ float g_t1 [MTOT*Dd];
__device__ float g_x1 [MTOT*Dd];
__device__ float g_x2 [MTOT*Dd];
__device__ float g_b3 [3*Dd];

// bf16 hi/lo buffers
__device__ __nv_bfloat16 g_xh [MTOT*Dd],  g_xl [MTOT*Dd];
__device__ __nv_bfloat16 g_x1h[MTOT*Dd],  g_x1l[MTOT*Dd];
__device__ __nv_bfloat16 g_x2h[MTOT*Dd],  g_x2l[MTOT*Dd];
__device__ __nv_bfloat16 g_cth[MTOT*Dd],  g_ctl[MTOT*Dd];
__device__ __nv_bfloat16 g_ffh[MTOT*FFd], g_ffl[MTOT*FFd];
__device__ __nv_bfloat16 g_tgh[Tt*Dd],    g_tgl[Tt*Dd];
__device__ __nv_bfloat16 g_qh [MTOT*Dd],  g_ql [MTOT*Dd];
__device__ __nv_bfloat16 g_kh [MTOT*Dd],  g_kl [MTOT*Dd];
__device__ __nv_bfloat16 g_vth[Dd*MTOT],  g_vtl[Dd*MTOT];   // V^T [n][m]
__device__ __nv_bfloat16 g_ckh[Tt*Dd],    g_ckl[Tt*Dd];
__device__ __nv_bfloat16 g_cvth[Dd*Tt],   g_cvtl[Dd*Tt];    // cross V^T

// transposed weights [N][K] hi/lo; wq,wk,wv contiguous -> fused QKV B = [2304][768]
#define WSZ  (Dd*Dd)
#define WOFF_FF1 (8*WSZ)
#define WOFF_FF2 (WOFF_FF1 + Dd*FFd)
#define WTOT (WOFF_FF2 + FFd*Dd)
__device__ __nv_bfloat16 g_wh[WTOT], g_wl[WTOT];

// =============== helpers =====================================================
__device__ __forceinline__ void mma16816(float* c, const uint32_t* a, const uint32_t* b) {
    asm volatile(
        "mma.sync.aligned.m16n8k16.row.col.f32.bf16.bf16.f32 "
        "{%0,%1,%2,%3}, {%4,%5,%6,%7}, {%8,%9}, {%0,%1,%2,%3};\n"
        : "+f"(c[0]), "+f"(c[1]), "+f"(c[2]), "+f"(c[3])
        : "r"(a[0]), "r"(a[1]), "r"(a[2]), "r"(a[3]), "r"(b[0]), "r"(b[1]));
}
__device__ __forceinline__ void ldsm4(uint32_t* r, uint32_t addr) {
    asm volatile("ldmatrix.sync.aligned.m8n8.x4.shared.b16 {%0,%1,%2,%3}, [%4];"
                 : "=r"(r[0]), "=r"(r[1]), "=r"(r[2]), "=r"(r[3]) : "r"(addr));
}
__device__ __forceinline__ uint32_t pack_bf2(__nv_bfloat16 a, __nv_bfloat16 b) {
    return ((uint32_t)__bfloat16_as_ushort(b) << 16) | (uint32_t)__bfloat16_as_ushort(a);
}
__device__ __forceinline__ uint32_t smem_u32(const void* p) {
    uint32_t a;
    asm("{ .reg .u64 t; cvta.to.shared.u64 t, %1; cvt.u32.u64 %0, t; }" : "=r"(a) : "l"(p));
    return a;
}
__device__ __forceinline__ void cpa16(uint32_t dst, const void* src, bool valid) {
    int sz = valid ? 16 : 0;
    asm volatile("cp.async.cg.shared.global [%0], [%1], 16, %2;"
                 :: "r"(dst), "l"(src), "r"(sz));
}
#define CP_COMMIT() asm volatile("cp.async.commit_group;" ::: "memory")
#define CP_WAIT(n)  asm volatile("cp.async.wait_group %0;" :: "n"(n) : "memory")

__device__ __forceinline__ void split_bf(float v, __nv_bfloat16& h, __nv_bfloat16& l) {
    h = __float2bfloat16(v);
    l = __float2bfloat16(v - __bfloat162float(h));
}

// ============ conversion kernels ============================================
__global__ void fconv(const float* __restrict__ x, __nv_bfloat16* __restrict__ h,
                      __nv_bfloat16* __restrict__ l, int n4)
{
    int i = blockIdx.x * 256 + threadIdx.x;
    if (i >= n4) return;
    float4 v = ((const float4*)x)[i];
    __nv_bfloat16 h0,h1,h2,h3,l0,l1,l2,l3;
    split_bf(v.x,h0,l0); split_bf(v.y,h1,l1); split_bf(v.z,h2,l2); split_bf(v.w,h3,l3);
    ((uint2*)h)[i] = make_uint2(pack_bf2(h0,h1), pack_bf2(h2,h3));
    ((uint2*)l)[i] = make_uint2(pack_bf2(l0,l1), pack_bf2(l2,l3));
}

__global__ void bcat3(const float* __restrict__ b0, const float* __restrict__ b1,
                      const float* __restrict__ b2, float* __restrict__ o)
{
    int i = blockIdx.x * 256 + threadIdx.x;
    if (i < Dd)            o[i] = b0[i];
    else if (i < 2*Dd)     o[i] = b1[i - Dd];
    else if (i < 3*Dd)     o[i] = b2[i - 2*Dd];
}

// fused weight transpose+split for all 10 weights in one launch
struct WAll {
    const float* W[10];
    __nv_bfloat16* Wh[10];
    __nv_bfloat16* Wl[10];
    int K[10], N[10], t0[10];
};

__global__ void wtconv_all(WAll d)
{
    __shared__ float t[32][33];
    const int bid = blockIdx.x;
    int w = 0;
    #pragma unroll
    for (int i = 1; i < 10; i++) if (bid >= d.t0[i]) w = i;
    const int K = d.K[w], N = d.N[w];
    const int tloc = bid - d.t0[w];
    const int nx = N >> 5;
    const int n0 = (tloc % nx) * 32, k0 = (tloc / nx) * 32;
    const float* W = d.W[w];
    __nv_bfloat16* Wh = d.Wh[w];
    __nv_bfloat16* Wl = d.Wl[w];

    const int tx = threadIdx.x, ty = threadIdx.y;   // 32 x 8
    #pragma unroll
    for (int i = 0; i < 4; i++)
        t[ty + i*8][tx] = W[(long)(k0 + ty + i*8) * N + n0 + tx];
    __syncthreads();
    #pragma unroll
    for (int i = 0; i < 4; i++) {
        int n = n0 + ty + i*8;
        float v = t[tx][ty + i*8];
        __nv_bfloat16 h, l; split_bf(v, h, l);
        Wh[(long)n * K + k0 + tx] = h;
        Wl[(long)n * K + k0 + tx] = l;
    }
}

// ======== split-bf16 tensor-core GEMM ========================================
// OMODE: 0 = fp32 C, 1 = bf16 hi/lo, 2 = bf16 hi/lo TRANSPOSED [n][m] (ldt)
#define STG_B 40960

template<int ACT, int RES, int OMODE>
__global__ void __launch_bounds__(256)
gemm_bf(const __nv_bfloat16* __restrict__ Ahp, const __nv_bfloat16* __restrict__ Alp,
        const __nv_bfloat16* __restrict__ Bhp, const __nv_bfloat16* __restrict__ Blp,
        const float* __restrict__ bias, const float* __restrict__ Rz,
        float* __restrict__ C, __nv_bfloat16* __restrict__ Chp, __nv_bfloat16* __restrict__ Clp,
        int M, int N, int K, int ldt)
{
    extern __shared__ char smem[];
    const uint32_t sb = smem_u32(smem);
    const int tid  = threadIdx.x;
    const int lane = tid & 31;
    const int wid  = tid >> 5;
    const int wm   = (wid & 1) * 64;
    const int wn   = (wid >> 1) * 32;
    const int bm   = blockIdx.y * 128;
    const int bn   = blockIdx.x * 128;
    const int nch  = K >> 5;
    const int gq = lane >> 2;
    const int gt = lane & 3;

    const int lrow = lane & 7, lmat = lane >> 3;
    const uint32_t aoff = (uint32_t)((lrow + (lmat & 1) * 8) * 80 + (lmat >> 1) * 16);
    const uint32_t boff = (uint32_t)((lrow + (lmat >> 1) * 8) * 80 + (lmat & 1) * 16);

    float acc[4][4][4];
    #pragma unroll
    for (int i = 0; i < 4; i++)
        #pragma unroll
        for (int j = 0; j < 4; j++)
            #pragma unroll
            for (int e = 0; e < 4; e++) acc[i][j][e] = 0.f;

    const __nv_bfloat16* srcs[4] = {Ahp, Alp, Bhp, Blp};

    auto load_stage = [&](int s, int k0) {
        #pragma unroll
        for (int a = 0; a < 4; a++) {
            #pragma unroll
            for (int t = 0; t < 2; t++) {
                int q   = tid + t * 256;
                int row = q >> 2, c4 = q & 3;
                int grow = (a < 2) ? (bm + row) : (bn + row);
                bool valid = (a < 2) ? (grow < M) : true;
                const __nv_bfloat16* src = srcs[a] + (long)(valid ? grow : 0) * K + k0 + c4 * 8;
                cpa16(sb + s * STG_B + a * 10240 + row * 80 + c4 * 16, src, valid);
            }
        }
    };

    load_stage(0, 0);
    CP_COMMIT();

    for (int c = 0; c < nch; c++) {
        if (c + 1 < nch) { load_stage((c + 1) & 1, (c + 1) * 32); CP_COMMIT(); CP_WAIT(1); }
        else             { CP_WAIT(0); }
        __syncthreads();

        const uint32_t stb = sb + (c & 1) * STG_B;
        const uint32_t sAh = stb, sAl = stb + 10240, sBh = stb + 20480, sBl = stb + 30720;

        #pragma unroll
        for (int ks = 0; ks < 2; ks++) {
            const uint32_t kof = ks * 32;
            uint32_t bh[4][2], bl[4][2];
            #pragma unroll
            for (int jp = 0; jp < 2; jp++) {
                uint32_t ad = (uint32_t)((wn + jp * 16) * 80) + kof;
                ldsm4(&bh[jp*2][0], sBh + ad + boff);
                ldsm4(&bl[jp*2][0], sBl + ad + boff);
            }
            #pragma unroll
            for (int i = 0; i < 4; i++) {
                uint32_t ad = (uint32_t)((wm + i * 16) * 80) + kof;
                uint32_t ahf[4], alf[4];
                ldsm4(ahf, sAh + ad + aoff);
                ldsm4(alf, sAl + ad + aoff);
                // pass-major: 4 independent accumulators between reuse
                #pragma unroll
                for (int j = 0; j < 4; j++) mma16816(acc[i][j], ahf, bh[j]);
                #pragma unroll
                for (int j = 0; j < 4; j++) mma16816(acc[i][j], alf, bh[j]);
                #pragma unroll
                for (int j = 0; j < 4; j++) mma16816(acc[i][j], ahf, bl[j]);
            }
        }
        __syncthreads();
    }

    #pragma unroll
    for (int i = 0; i < 4; i++) {
        #pragma unroll
        for (int rr = 0; rr < 2; rr++) {
            int m = bm + wm + i * 16 + gq + rr * 8;
            if (m >= M) continue;
            #pragma unroll
            for (int j = 0; j < 4; j++) {
                int n = bn + wn + j * 8 + gt * 2;
                float v0 = acc[i][j][rr * 2 + 0] + __ldg(&bias[n]);
                float v1 = acc[i][j][rr * 2 + 1] + __ldg(&bias[n + 1]);
                if (RES) {
                    const float* rp = Rz + (long)m * N + n;
                    v0 += rp[0]; v1 += rp[1];
                }
                if (ACT) {
                    v0 = 0.5f * v0 * (1.0f + erff(v0 * 0.70710678118654752f));
                    v1 = 0.5f * v1 * (1.0f + erff(v1 * 0.70710678118654752f));
                }
                if (OMODE == 0)
                    *(float2*)(C + (long)m * N + n) = make_float2(v0, v1);
                if (OMODE == 1) {
                    __nv_bfloat16 h0,h1,l0,l1;
                    split_bf(v0,h0,l0); split_bf(v1,h1,l1);
                    *(uint32_t*)(Chp + (long)m * N + n) = pack_bf2(h0,h1);
                    *(uint32_t*)(Clp + (long)m * N + n) = pack_bf2(l0,l1);
                }
                if (OMODE == 2) {
                    __nv_bfloat16 h0,h1,l0,l1;
                    split_bf(v0,h0,l0); split_bf(v1,h1,l1);
                    Chp[(long)n * ldt + m]       = h0;
                    Chp[(long)(n + 1) * ldt + m] = h1;
                    Clp[(long)n * ldt + m]       = l0;
                    Clp[(long)(n + 1) * ldt + m] = l1;
                }
            }
        }
    }
}

// ======== fused QKV projection: N=2304, B = concatenated wq|wk|wv ============
__global__ void __launch_bounds__(256)
gemm_qkv(const __nv_bfloat16* __restrict__ Ahp, const __nv_bfloat16* __restrict__ Alp,
         const __nv_bfloat16* __restrict__ Bhp, const __nv_bfloat16* __restrict__ Blp,
         const float* __restrict__ bias3,
         __nv_bfloat16* __restrict__ qh, __nv_bfloat16* __restrict__ ql,
         __nv_bfloat16* __restrict__ kh, __nv_bfloat16* __restrict__ kl,
         __nv_bfloat16* __restrict__ vth, __nv_bfloat16* __restrict__ vtl,
         int M, int ldt)
{
    extern __shared__ char smem[];
    const uint32_t sb = smem_u32(smem);
    const int tid  = threadIdx.x;
    const int lane = tid & 31;
    const int wid  = tid >> 5;
    const int wm   = (wid & 1) * 64;
    const int wn   = (wid >> 1) * 32;
    const int bm   = blockIdx.y * 128;
    const int bn   = blockIdx.x * 128;
    const int K    = Dd;
    const int nch  = K >> 5;
    const int gq = lane >> 2;
    const int gt = lane & 3;

    const int lrow = lane & 7, lmat = lane >> 3;
    const uint32_t aoff = (uint32_t)((lrow + (lmat & 1) * 8) * 80 + (lmat >> 1) * 16);
    const uint32_t boff = (uint32_t)((lrow + (lmat >> 1) * 8) * 80 + (lmat & 1) * 16);

    float acc[4][4][4];
    #pragma unroll
    for (int i = 0; i < 4; i++)
        #pragma unroll
        for (int j = 0; j < 4; j++)
            #pragma unroll
            for (int e = 0; e < 4; e++) acc[i][j][e] = 0.f;

    const __nv_bfloat16* srcs[4] = {Ahp, Alp, Bhp, Blp};

    auto load_stage = [&](int s, int k0) {
        #pragma unroll
        for (int a = 0; a < 4; a++) {
            #pragma unroll
            for (int t = 0; t < 2; t++) {
                int q   = tid + t * 256;
                int row = q >> 2, c4 = q & 3;
                int grow = (a < 2) ? (bm + row) : (bn + row);
                const __nv_bfloat16* src = srcs[a] + (long)grow * K + k0 + c4 * 8;
                cpa16(sb + s * STG_B + a * 10240 + row * 80 + c4 * 16, src, true);
            }
        }
    };

    load_stage(0, 0);
    CP_COMMIT();

    for (int c = 0; c < nch; c++) {
        if (c + 1 < nch) { load_stage((c + 1) & 1, (c + 1) * 32); CP_COMMIT(); CP_WAIT(1); }
        else             { CP_WAIT(0); }
        __syncthreads();

        const uint32_t stb = sb + (c & 1) * STG_B;
        const uint32_t sAh = stb, sAl = stb + 10240, sBh = stb + 20480, sBl = stb + 30720;

        #pragma unroll
        for (int ks = 0; ks < 2; ks++) {
            const uint32_t kof = ks * 32;
            uint32_t bh[4][2], bl[4][2];
            #pragma unroll
            for (int jp = 0; jp < 2; jp++) {
                uint32_t ad = (uint32_t)((wn + jp * 16) * 80) + kof;
                ldsm4(&bh[jp*2][0], sBh + ad + boff);
                ldsm4(&bl[jp*2][0], sBl + ad + boff);
            }
            #pragma unroll
            for (int i = 0; i < 4; i++) {
                uint32_t ad = (uint32_t)((wm + i * 16) * 80) + kof;
                uint32_t ahf[4], alf[4];
                ldsm4(ahf, sAh + ad + aoff);
                ldsm4(alf, sAl + ad + aoff);
                #pragma unroll
                for (int j = 0; j < 4; j++) mma16816(acc[i][j], ahf, bh[j]);
                #pragma unroll
                for (int j = 0; j < 4; j++) mma16816(acc[i][j], alf, bh[j]);
                #pragma unroll
                for (int j = 0; j < 4; j++) mma16816(acc[i][j], ahf, bl[j]);
            }
        }
        __syncthreads();
    }

    const int seg = bn / Dd;     // 0=Q, 1=K, 2=V  (128-tiles never straddle: 768%128==0)
    #pragma unroll
    for (int i = 0; i < 4; i++) {
        #pragma unroll
        for (int rr = 0; rr < 2; rr++) {
            int m = bm + wm + i * 16 + gq + rr * 8;
            #pragma unroll
            for (int j = 0; j < 4; j++) {
                int n = bn + wn + j * 8 + gt * 2;
                float v0 = acc[i][j][rr * 2 + 0] + __ldg(&bias3[n]);
                float v1 = acc[i][j][rr * 2 + 1] + __ldg(&bias3[n + 1]);
                int ln_ = n - seg * Dd;
                __nv_bfloat16 h0,h1,l0,l1;
                split_bf(v0,h0,l0); split_bf(v1,h1,l1);
                if (seg == 0) {
                    *(uint32_t*)(qh + (long)m * Dd + ln_) = pack_bf2(h0,h1);
                    *(uint32_t*)(ql + (long)m * Dd + ln_) = pack_bf2(l0,l1);
                } else if (seg == 1) {
                    *(uint32_t*)(kh + (long)m * Dd + ln_) = pack_bf2(h0,h1);
                    *(uint32_t*)(kl + (long)m * Dd + ln_) = pack_bf2(l0,l1);
                } else {
                    vth[(long)ln_ * ldt + m]       = h0;
                    vth[(long)(ln_ + 1) * ldt + m] = h1;
                    vtl[(long)ln_ * ldt + m]       = l0;
                    vtl[(long)(ln_ + 1) * ldt + m] = l1;
                }
            }
        }
    }
}

// ============ tensor-core flash attention (split bf16) =======================
#define ATS   144
#define AROWB 9216
#define ASTG0 (2*AROWB)
#define ASTGSZ (4*AROWB)
#define ASMEM (ASTG0 + 2*ASTGSZ)  // 92160

__global__ void __launch_bounds__(128)
attn_mma(const __nv_bfloat16* __restrict__ Qh, const __nv_bfloat16* __restrict__ Ql,
         const __nv_bfloat16* __restrict__ Kh, const __nv_bfloat16* __restrict__ Kl,
         const __nv_bfloat16* __restrict__ Vth, const __nv_bfloat16* __restrict__ Vtl,
         __nv_bfloat16* __restrict__ Oh, __nv_bfloat16* __restrict__ Ol,
         int Sk, int kvRowPB, int vtColPB, int ldv, int band)
{
    extern __shared__ char sm[];
    const uint32_t sb = smem_u32(sm);
    const int tid = threadIdx.x;
    const int wq  = tid >> 5;
    const int lane = tid & 31;
    const int gq = lane >> 2, gt = lane & 3;
    const int b = blockIdx.z, h = blockIdx.y, q0 = blockIdx.x * 64;

    const int lrow = lane & 7, lmat = lane >> 3;
    const uint32_t aoffA = (uint32_t)((lrow + (lmat & 1) * 8) * ATS + (lmat >> 1) * 16);
    const uint32_t boffA = (uint32_t)((lrow + (lmat >> 1) * 8) * ATS + (lmat & 1) * 16);

    // Q tile (loaded once)
    {
        const __nv_bfloat16* qsrc[2] = {Qh, Ql};
        #pragma unroll
        for (int a = 0; a < 2; a++) {
            const __nv_bfloat16* src = qsrc[a] + ((long)(b * Ss + q0)) * Dd + h * DHd;
            #pragma unroll
            for (int it = 0; it < 4; it++) {
                int idx = it * 128 + tid, row = idx >> 3, c4 = idx & 7;
                cpa16(sb + a * AROWB + row * ATS + c4 * 16, src + (long)row * Dd + c4 * 8, true);
            }
        }
    }
    auto loadKV = [&](int stg, int k0) {
        uint32_t so = sb + ASTG0 + (stg & 1) * ASTGSZ;
        const __nv_bfloat16* ks[2] = {Kh, Kl};
        #pragma unroll
        for (int a = 0; a < 2; a++) {
            const __nv_bfloat16* src = ks[a] + ((long)(kvRowPB * b + k0)) * Dd + h * DHd;
            #pragma unroll
            for (int it = 0; it < 4; it++) {
                int idx = it * 128 + tid, row = idx >> 3, c4 = idx & 7;
                cpa16(so + a * AROWB + row * ATS + c4 * 16, src + (long)row * Dd + c4 * 8, true);
            }
        }
        const __nv_bfloat16* vs[2] = {Vth, Vtl};
        #pragma unroll
        for (int a = 0; a < 2; a++) {
            const __nv_bfloat16* src = vs[a] + (long)(h * DHd) * ldv + (long)vtColPB * b + k0;
            #pragma unroll
            for (int it = 0; it < 4; it++) {
                int idx = it * 128 + tid, row = idx >> 3, c4 = idx & 7;
                cpa16(so + (2 + a) * AROWB + row * ATS + c4 * 16, src + (long)row * ldv + c4 * 8, true);
            }
        }
    };
    loadKV(0, 0);
    CP_COMMIT();

    float m0 = -1e30f, m1 = -1e30f, l0 = 0.f, l1 = 0.f;
    float o[8][4];
    #pragma unroll
    for (int j = 0; j < 8; j++)
        #pragma unroll
        for (int e = 0; e < 4; e++) o[j][e] = 0.f;
    uint32_t qfh[4][4], qfl[4][4];

    const int nkt = Sk >> 6;
    for (int t = 0; t < nkt; t++) {
        if (t + 1 < nkt) { loadKV(t + 1, (t + 1) * 64); CP_COMMIT(); CP_WAIT(1); }
        else             { CP_WAIT(0); }
        __syncthreads();

        if (t == 0) {
            const uint32_t qb0 = sb + (uint32_t)(wq * 16 * ATS);
            #pragma unroll
            for (int s = 0; s < 4; s++) {
                ldsm4(qfh[s], qb0 + s * 32 + aoffA);
                ldsm4(qfl[s], qb0 + AROWB + s * 32 + aoffA);
            }
        }

        const uint32_t stb = sb + ASTG0 + (t & 1) * ASTGSZ;
        const uint32_t sKh = stb, sKl = stb + AROWB;
        const uint32_t sVh = stb + 2 * AROWB, sVl = stb + 3 * AROWB;

        // ---- scores S = Q K^T  (two jp-tiles interleaved: 4 indep accs) ----
        float sc[8][4];
        #pragma unroll
        for (int j = 0; j < 8; j++)
            #pragma unroll
            for (int e = 0; e < 4; e++) sc[j][e] = 0.f;

        #pragma unroll
        for (int jpp = 0; jpp < 2; jpp++) {
            uint32_t ad0 = (uint32_t)((jpp * 2)     * 16 * ATS);
            uint32_t ad1 = (uint32_t)((jpp * 2 + 1) * 16 * ATS);
            int j0 = 4 * jpp;
            #pragma unroll
            for (int s = 0; s < 4; s++) {
                uint32_t kha[4], kla[4], khb[4], klb[4];
                ldsm4(kha, sKh + ad0 + s * 32 + boffA);
                ldsm4(kla, sKl + ad0 + s * 32 + boffA);
                ldsm4(khb, sKh + ad1 + s * 32 + boffA);
                ldsm4(klb, sKl + ad1 + s * 32 + boffA);
                mma16816(sc[j0+0], qfh[s], &kha[0]);
                mma16816(sc[j0+1], qfh[s], &kha[2]);
                mma16816(sc[j0+2], qfh[s], &khb[0]);
                mma16816(sc[j0+3], qfh[s], &khb[2]);
                mma16816(sc[j0+0], qfl[s], &kha[0]);
                mma16816(sc[j0+1], qfl[s], &kha[2]);
                mma16816(sc[j0+2], qfl[s], &khb[0]);
                mma16816(sc[j0+3], qfl[s], &khb[2]);
                mma16816(sc[j0+0], qfh[s], &kla[0]);
                mma16816(sc[j0+1], qfh[s], &kla[2]);
                mma16816(sc[j0+2], qfh[s], &klb[0]);
                mma16816(sc[j0+3], qfh[s], &klb[2]);
            }
        }

        const int k0 = t * 64;
        const int qi0 = q0 + wq * 16 + gq, qi1 = qi0 + 8;
        #pragma unroll
        for (int j = 0; j < 8; j++) {
            int ki0 = k0 + j * 8 + gt * 2, ki1 = ki0 + 1;
            if (band) {
                int d00 = qi0 - ki0; d00 = d00 < 0 ? -d00 : d00;
                int d01 = qi0 - ki1; d01 = d01 < 0 ? -d01 : d01;
                int d10 = qi1 - ki0; d10 = d10 < 0 ? -d10 : d10;
                int d11 = qi1 - ki1; d11 = d11 < 0 ? -d11 : d11;
                sc[j][0] = sc[j][0] * 0.125f + (d00 <= Rr ? 1.f : 0.f);
                sc[j][1] = sc[j][1] * 0.125f + (d01 <= Rr ? 1.f : 0.f);
                sc[j][2] = sc[j][2] * 0.125f + (d10 <= Rr ? 1.f : 0.f);
                sc[j][3] = sc[j][3] * 0.125f + (d11 <= Rr ? 1.f : 0.f);
            } else {
                sc[j][0] *= 0.125f; sc[j][1] *= 0.125f;
                sc[j][2] *= 0.125f; sc[j][3] *= 0.125f;
            }
        }

        // ---- online softmax ----
        float nm0 = -1e30f, nm1 = -1e30f;
        #pragma unroll
        for (int j = 0; j < 8; j++) {
            nm0 = fmaxf(nm0, fmaxf(sc[j][0], sc[j][1]));
            nm1 = fmaxf(nm1, fmaxf(sc[j][2], sc[j][3]));
        }
        nm0 = fmaxf(nm0, __shfl_xor_sync(0xffffffffu, nm0, 1));
        nm0 = fmaxf(nm0, __shfl_xor_sync(0xffffffffu, nm0, 2));
        nm1 = fmaxf(nm1, __shfl_xor_sync(0xffffffffu, nm1, 1));
        nm1 = fmaxf(nm1, __shfl_xor_sync(0xffffffffu, nm1, 2));
        float M0 = fmaxf(m0, nm0), M1 = fmaxf(m1, nm1);
        float f0 = __expf(m0 - M0), f1 = __expf(m1 - M1);
        m0 = M0; m1 = M1;

        float s0 = 0.f, s1 = 0.f;
        #pragma unroll
        for (int j = 0; j < 8; j++) {
            sc[j][0] = __expf(sc[j][0] - M0);
            sc[j][1] = __expf(sc[j][1] - M0);
            sc[j][2] = __expf(sc[j][2] - M1);
            sc[j][3] = __expf(sc[j][3] - M1);
            s0 += sc[j][0] + sc[j][1];
            s1 += sc[j][2] + sc[j][3];
        }
        s0 += __shfl_xor_sync(0xffffffffu, s0, 1);
        s0 += __shfl_xor_sync(0xffffffffu, s0, 2);
        s1 += __shfl_xor_sync(0xffffffffu, s1, 1);
        s1 += __shfl_xor_sync(0xffffffffu, s1, 2);
        l0 = l0 * f0 + s0;
        l1 = l1 * f1 + s1;

        #pragma unroll
        for (int j = 0; j < 8; j++) {
            o[j][0] *= f0; o[j][1] *= f0;
            o[j][2] *= f1; o[j][3] *= f1;
        }

        // ---- P fragments (bf16 hi/lo) ----
        uint32_t ph[4][4], pl[4][4];
        #pragma unroll
        for (int s = 0; s < 4; s++) {
            __nv_bfloat16 h0,h1,lo0,lo1;
            split_bf(sc[2*s][0], h0, lo0); split_bf(sc[2*s][1], h1, lo1);
            ph[s][0] = pack_bf2(h0,h1); pl[s][0] = pack_bf2(lo0,lo1);
            split_bf(sc[2*s][2], h0, lo0); split_bf(sc[2*s][3], h1, lo1);
            ph[s][1] = pack_bf2(h0,h1); pl[s][1] = pack_bf2(lo0,lo1);
            split_bf(sc[2*s+1][0], h0, lo0); split_bf(sc[2*s+1][1], h1, lo1);
            ph[s][2] = pack_bf2(h0,h1); pl[s][2] = pack_bf2(lo0,lo1);
            split_bf(sc[2*s+1][2], h0, lo0); split_bf(sc[2*s+1][3], h1, lo1);
            ph[s][3] = pack_bf2(h0,h1); pl[s][3] = pack_bf2(lo0,lo1);
        }

        // ---- O += P V  (two jp-tiles interleaved) ----
        #pragma unroll
        for (int jpp = 0; jpp < 2; jpp++) {
            uint32_t ad0 = (uint32_t)((jpp * 2)     * 16 * ATS);
            uint32_t ad1 = (uint32_t)((jpp * 2 + 1) * 16 * ATS);
            int j0 = 4 * jpp;
            #pragma unroll
            for (int s = 0; s < 4; s++) {
                uint32_t vha[4], vla[4], vhb[4], vlb[4];
                ldsm4(vha, sVh + ad0 + s * 32 + boffA);
                ldsm4(vla, sVl + ad0 + s * 32 + boffA);
                ldsm4(vhb, sVh + ad1 + s * 32 + boffA);
                ldsm4(vlb, sVl + ad1 + s * 32 + boffA);
                mma16816(o[j0+0], ph[s], &vha[0]);
                mma16816(o[j0+1], ph[s], &vha[2]);
                mma16816(o[j0+2], ph[s], &vhb[0]);
                mma16816(o[j0+3], ph[s], &vhb[2]);
                mma16816(o[j0+0], pl[s], &vha[0]);
                mma16816(o[j0+1], pl[s], &vha[2]);
                mma16816(o[j0+2], pl[s], &vhb[0]);
                mma16816(o[j0+3], pl[s], &vhb[2]);
                mma16816(o[j0+0], ph[s], &vla[0]);
                mma16816(o[j0+1], ph[s], &vla[2]);
                mma16816(o[j0+2], ph[s], &vlb[0]);
                mma16816(o[j0+3], ph[s], &vlb[2]);
            }
        }
        __syncthreads();
    }

    // ---- write ctx as bf16 hi/lo ----
    float i0 = 1.f / l0, i1 = 1.f / l1;
    long r0g = (long)(b * Ss) + q0 + wq * 16 + gq;
    #pragma unroll
    for (int jd = 0; jd < 8; jd++) {
        int col = h * DHd + jd * 8 + gt * 2;
        float v0 = o[jd][0] * i0, v1 = o[jd][1] * i0;
        float v2 = o[jd][2] * i1, v3 = o[jd][3] * i1;
        __nv_bfloat16 h0,h1,lo0,lo1;
        split_bf(v0,h0,lo0); split_bf(v1,h1,lo1);
        *(uint32_t*)(Oh + r0g * Dd + col) = pack_bf2(h0,h1);
        *(uint32_t*)(Ol + r0g * Dd + col) = pack_bf2(lo0,lo1);
        split_bf(v2,h0,lo0); split_bf(v3,h1,lo1);
        *(uint32_t*)(Oh + (r0g + 8) * Dd + col) = pack_bf2(h0,h1);
        *(uint32_t*)(Ol + (r0g + 8) * Dd + col) = pack_bf2(lo0,lo1);
    }
}

// ---------------- LayerNorm ---------------------------------------------
__global__ __launch_bounds__(256)
void ln_kernel(const float* __restrict__ in, const float* __restrict__ g,
               const float* __restrict__ bta, float* __restrict__ out,
               __nv_bfloat16* __restrict__ oh, __nv_bfloat16* __restrict__ ol)
{
    const int row = blockIdx.x;
    const float* x = in + (long)row * Dd;
    const int tid = threadIdx.x;

    float v0 = x[tid], v1 = x[tid + 256], v2 = x[tid + 512];
    float s = v0 + v1 + v2;

    __shared__ float sred[8];
    __shared__ float smean, svar;

    #pragma unroll
    for (int off = 16; off; off >>= 1) s += __shfl_xor_sync(0xffffffffu, s, off);
    if ((tid & 31) == 0) sred[tid >> 5] = s;
    __syncthreads();
    if (tid == 0) {
        float t = 0.f;
        #pragma unroll
        for (int i = 0; i < 8; i++) t += sred[i];
        smean = t * (1.0f / Dd);
    }
    __syncthreads();
    float m = smean;
    float d0 = v0 - m, d1 = v1 - m, d2 = v2 - m;
    float sq = d0*d0 + d1*d1 + d2*d2;
    #pragma unroll
    for (int off = 16; off; off >>= 1) sq += __shfl_xor_sync(0xffffffffu, sq, off);
    if ((tid & 31) == 0) sred[tid >> 5] = sq;
    __syncthreads();
    if (tid == 0) {
        float t = 0.f;
        #pragma unroll
        for (int i = 0; i < 8; i++) t += sred[i];
        svar = t * (1.0f / Dd);
    }
    __syncthreads();
    float inv = rsqrtf(svar + 1e-12f);
    #pragma unroll
    for (int u = 0; u < 3; u++) {
        int idx = tid + u * 256;
        float d = (u == 0 ? d0 : (u == 1 ? d1 : d2));
        float val = d * inv * g[idx] + bta[idx];
        out[(long)row * Dd + idx] = val;
        if (oh) {
            __nv_bfloat16 hh, ll; split_bf(val, hh, ll);
            oh[(long)row * Dd + idx] = hh;
            ol[(long)row * Dd + idx] = ll;
        }
    }
}

// ---------------- launch ----------------------------------------------------
typedef void (*gemm_fn)(const __nv_bfloat16*, const __nv_bfloat16*,
                        const __nv_bfloat16*, const __nv_bfloat16*,
                        const float*, const float*,
                        float*, __nv_bfloat16*, __nv_bfloat16*, int, int, int, int);

static inline void launch_gemm_t(gemm_fn fn,
                                 const __nv_bfloat16* Ah, const __nv_bfloat16* Al,
                                 const __nv_bfloat16* Bh, const __nv_bfloat16* Bl,
                                 const float* bias, const float* Rz,
                                 float* C, __nv_bfloat16* Ch, __nv_bfloat16* Cl,
                                 int M, int N, int K, int ldt)
{
    dim3 g(N / 128, (M + 127) / 128);
    cudaFuncSetAttribute((const void*)fn, cudaFuncAttributeMaxDynamicSharedMemorySize, 2 * STG_B);
    fn<<<g, 256, 2 * STG_B>>>(Ah, Al, Bh, Bl, bias, Rz, C, Ch, Cl, M, N, K, ldt);
}

extern "C" void kernel_launch(void* const* d_in, const int* in_sizes, int n_in,
                              void* d_out, int out_size)
{
    const float* X     = (const float*)d_in[0];
    const float* tag   = (const float*)d_in[1];
    const float* sa_wq = (const float*)d_in[2];  const float* sa_bq = (const float*)d_in[3];
    const float* sa_wk = (const float*)d_in[4];  const float* sa_bk = (const float*)d_in[5];
    const float* sa_wv = (const float*)d_in[6];  const float* sa_bv = (const float*)d_in[7];
    const float* sa_wo = (const float*)d_in[8];  const float* sa_bo = (const float*)d_in[9];
    const float* sa_lg = (const float*)d_in[10]; const float* sa_lb = (const float*)d_in[11];
    const float* ca_wq = (const float*)d_in[12]; const float* ca_bq = (const float*)d_in[13];
    const float* ca_wk = (const float*)d_in[14]; const float* ca_bk = (const float*)d_in[15];
    const float* ca_wv = (const float*)d_in[16]; const float* ca_bv = (const float*)d_in[17];
    const float* ca_wo = (const float*)d_in[18]; const float* ca_bo = (const float*)d_in[19];
    const float* ca_lg = (const float*)d_in[20]; const float* ca_lb = (const float*)d_in[21];
    const float* ff_w1 = (const float*)d_in[22]; const float* ff_b1 = (const float*)d_in[23];
    const float* ff_w2 = (const float*)d_in[24]; const float* ff_b2 = (const float*)d_in[25];
    const float* ff_lg = (const float*)d_in[26]; const float* ff_lb = (const float*)d_in[27];
    float* out = (float*)d_out;

    float *t1, *x1, *x2, *b3;
    cudaGetSymbolAddress((void**)&t1, g_t1);
    cudaGetSymbolAddress((void**)&x1, g_x1); cudaGetSymbolAddress((void**)&x2, g_x2);
    cudaGetSymbolAddress((void**)&b3, g_b3);

    __nv_bfloat16 *xh,*xl,*x1h,*x1l,*x2h,*x2l,*cth,*ctl,*ffh,*ffl,*tgh,*tgl,*wh,*wl;
    __nv_bfloat16 *qh,*ql,*kh,*kl,*vth,*vtl,*ckh,*ckl,*cvth,*cvtl;
    cudaGetSymbolAddress((void**)&xh,  g_xh);  cudaGetSymbolAddress((void**)&xl,  g_xl);
    cudaGetSymbolAddress((void**)&x1h, g_x1h); cudaGetSymbolAddress((void**)&x1l, g_x1l);
    cudaGetSymbolAddress((void**)&x2h, g_x2h); cudaGetSymbolAddress((void**)&x2l, g_x2l);
    cudaGetSymbolAddress((void**)&cth, g_cth); cudaGetSymbolAddress((void**)&ctl, g_ctl);
    cudaGetSymbolAddress((void**)&ffh, g_ffh); cudaGetSymbolAddress((void**)&ffl, g_ffl);
    cudaGetSymbolAddress((void**)&tgh, g_tgh); cudaGetSymbolAddress((void**)&tgl, g_tgl);
    cudaGetSymbolAddress((void**)&wh,  g_wh);  cudaGetSymbolAddress((void**)&wl,  g_wl);
    cudaGetSymbolAddress((void**)&qh,  g_qh);  cudaGetSymbolAddress((void**)&ql,  g_ql);
    cudaGetSymbolAddress((void**)&kh,  g_kh);  cudaGetSymbolAddress((void**)&kl,  g_kl);
    cudaGetSymbolAddress((void**)&vth, g_vth); cudaGetSymbolAddress((void**)&vtl, g_vtl);
    cudaGetSymbolAddress((void**)&ckh, g_ckh); cudaGetSymbolAddress((void**)&ckl, g_ckl);
    cudaGetSymbolAddress((void**)&cvth,g_cvth);cudaGetSymbolAddress((void**)&cvtl,g_cvtl);

    const int M = MTOT;
    dim3 agrid(Ss / 64, Hh, Bb);
    dim3 tb(32, 8);

    cudaFuncSetAttribute(attn_mma, cudaFuncAttributeMaxDynamicSharedMemorySize, ASMEM);
    cudaFuncSetAttribute(gemm_qkv, cudaFuncAttributeMaxDynamicSharedMemorySize, 2 * STG_B);

    // ---- pre-convert activations, biases & weights ----
    fconv<<<(M*Dd/4 + 255)/256, 256>>>(X, xh, xl, M*Dd/4);
    fconv<<<(Tt*Dd/4 + 255)/256, 256>>>(tag, tgh, tgl, Tt*Dd/4);
    bcat3<<<9, 256>>>(sa_bq, sa_bk, sa_bv, b3);

    {
        const float* ws[10]  = {sa_wq, sa_wk, sa_wv, sa_wo, ca_wq, ca_wk, ca_wv, ca_wo, ff_w1, ff_w2};
        const long  woff[10] = {0, WSZ, 2*WSZ, 3*WSZ, 4*WSZ, 5*WSZ, 6*WSZ, 7*WSZ, WOFF_FF1, WOFF_FF2};
        const int   wk_[10]  = {Dd,Dd,Dd,Dd,Dd,Dd,Dd,Dd,Dd,FFd};
        const int   wn_[10]  = {Dd,Dd,Dd,Dd,Dd,Dd,Dd,Dd,FFd,Dd};
        WAll wa;
        int cum = 0;
        for (int i = 0; i < 10; i++) {
            wa.W[i] = ws[i]; wa.Wh[i] = wh + woff[i]; wa.Wl[i] = wl + woff[i];
            wa.K[i] = wk_[i]; wa.N[i] = wn_[i]; wa.t0[i] = cum;
            cum += (wk_[i] / 32) * (wn_[i] / 32);
        }
        wtconv_all<<<cum, tb>>>(wa);
    }

    // ---- self-attention (fused QKV projection) ----
    {
        dim3 g(3 * Dd / 128, M / 128);   // 18 x 32 = 576 CTAs
        gemm_qkv<<<g, 256, 2 * STG_B>>>(xh, xl, wh, wl, b3,
                                        qh, ql, kh, kl, vth, vtl, M, MTOT);
    }
    attn_mma<<<agrid, 128, ASMEM>>>(qh, ql, kh, kl, vth, vtl, cth, ctl, Ss, Ss, Ss, MTOT, 1);
    launch_gemm_t(gemm_bf<0,1,0>, cth, ctl, wh+3*WSZ, wl+3*WSZ, sa_bo, X, t1, nullptr, nullptr, M, Dd, Dd, 0);
    ln_kernel<<<M, 256>>>(t1, sa_lg, sa_lb, x1, x1h, x1l);

    // ---- cross-attention ----
    launch_gemm_t(gemm_bf<0,0,1>, x1h, x1l, wh+4*WSZ, wl+4*WSZ, ca_bq, nullptr, nullptr, qh, ql, M, Dd, Dd, 0);
    launch_gemm_t(gemm_bf<0,0,1>, tgh, tgl, wh+5*WSZ, wl+5*WSZ, ca_bk, nullptr, nullptr, ckh, ckl, Tt, Dd, Dd, 0);
    launch_gemm_t(gemm_bf<0,0,2>, tgh, tgl, wh+6*WSZ, wl+6*WSZ, ca_bv, nullptr, nullptr, cvth, cvtl, Tt, Dd, Dd, Tt);
    attn_mma<<<agrid, 128, ASMEM>>>(qh, ql, ckh, ckl, cvth, cvtl, cth, ctl, Tt, 0, 0, Tt, 0);
    launch_gemm_t(gemm_bf<0,1,0>, cth, ctl, wh+7*WSZ, wl+7*WSZ, ca_bo, x1, t1, nullptr, nullptr, M, Dd, Dd, 0);
    ln_kernel<<<M, 256>>>(t1, ca_lg, ca_lb, x2, x2h, x2l);

    // ---- FFN ----
    launch_gemm_t(gemm_bf<1,0,1>, x2h, x2l, wh+WOFF_FF1, wl+WOFF_FF1, ff_b1, nullptr, nullptr, ffh, ffl, M, FFd, Dd, 0);
    launch_gemm_t(gemm_bf<0,1,0>, ffh, ffl, wh+WOFF_FF2, wl+WOFF_FF2, ff_b2, x2, t1, nullptr, nullptr, M, Dd, FFd, 0);
    ln_kernel<<<M, 256>>>(t1, ff_lg, ff_lb, out, nullptr, nullptr);
}